// round 5
// baseline (speedup 1.0000x reference)
#include <cuda_runtime.h>
#include <math.h>

// Problem constants
#define NN    4096      // nodes
#define HDIM  32
#define TROLL 200
#define FIN   5
#define KSPLIT 8        // K-split factor for per-step GEMM
#define KCHUNK (NN / KSPLIT)   // 512

// GEMM tile config
#define BM 256
#define BN 64
#define BK 16

typedef unsigned long long u64;

__device__ __forceinline__ u64 pack2(float x, float y) {
    u64 r;
    asm("mov.b64 %0, {%1, %2};" : "=l"(r) : "f"(x), "f"(y));
    return r;
}
__device__ __forceinline__ void unpack2(u64 v, float& x, float& y) {
    asm("mov.b64 {%0, %1}, %2;" : "=f"(x), "=f"(y) : "l"(v));
}
__device__ __forceinline__ void ffma2(u64& d, u64 a, u64 b) {
    asm("fma.rn.f32x2 %0, %1, %2, %0;" : "+l"(d) : "l"(a), "l"(b));
}

// ---------------- device scratch (allocation-free: __device__ globals) ------
__device__ __align__(16) float g_HC[NN * 64];               // [n][0:32]=h, [32:64]=c
__device__ __align__(16) float g_Mpart[(size_t)KSPLIT * NN * 64]; // K-split partials of A@[h|c]
__device__ __align__(16) float g_Xr[(size_t)NN * 1024];     // X rearranged [k][t*5+f], padded to 1024
__device__ __align__(16) float g_C1[(size_t)NN * 1024];     // A @ Xr
__device__ __align__(16) float g_U[101 * 128];              // fused gate matrix
__device__ __align__(16) float g_bias[128];                 // b_ih + b_hh

// ---------------- setup: build fused gate matrix U --------------------------
// gates[n,j] = bias[j] + sum_k v[n,k] * U[k,j]
//   v = [ (A@h)[0:32] | (A@c)[0:32] | h[0:32] | (A@x_t)[0:5] ]
__global__ void setup_kernel(const float* __restrict__ Wx, const float* __restrict__ Wh,
                             const float* __restrict__ Wc, const float* __restrict__ W_ih,
                             const float* __restrict__ W_hh, const float* __restrict__ b_ih,
                             const float* __restrict__ b_hh) {
    const int j = threadIdx.x;  // 0..127 gate column
    __shared__ float sWih[128 * 32];
    for (int i = j; i < 128 * 32; i += 128) sWih[i] = W_ih[i];
    __syncthreads();

    for (int r = 0; r < 32; r++) {
        float s = 0.f;
        for (int m = 0; m < 32; m++) s += Wh[r * 32 + m] * sWih[j * 32 + m];
        g_U[r * 128 + j] = s;
    }
    for (int r = 0; r < 32; r++) {
        float s = 0.f;
        for (int m = 0; m < 32; m++) s += Wc[r * 32 + m] * sWih[j * 32 + m];
        g_U[(32 + r) * 128 + j] = s;
    }
    for (int m = 0; m < 32; m++) g_U[(64 + m) * 128 + j] = W_hh[j * 32 + m];
    for (int f = 0; f < FIN; f++) {
        float s = 0.f;
        for (int m = 0; m < 32; m++) s += Wx[f * 32 + m] * sWih[j * 32 + m];
        g_U[(96 + f) * 128 + j] = s;
    }
    g_bias[j] = b_ih[j] + b_hh[j];
}

__global__ void zero_hc_kernel() {
    int i = blockIdx.x * blockDim.x + threadIdx.x;
    if (i < NN * 64) g_HC[i] = 0.f;
}

// Rearrange X[t][k][f] -> Xr[k][t*5+f], zero-pad cols 1000..1023
__global__ void xr_kernel(const float* __restrict__ X) {
    int idx = blockIdx.x * blockDim.x + threadIdx.x;   // over NN*1024
    int k = idx >> 10;
    int q = idx & 1023;
    float v = 0.f;
    if (q < TROLL * FIN) {
        int t = q / FIN;
        int f = q - t * FIN;
        v = X[(size_t)t * (NN * FIN) + k * FIN + f];
    }
    g_Xr[idx] = v;
}

// ---------------- tiled fp32 GEMM with packed FFMA2 --------------------------
// C[z] = A[rows, krange] @ B. Block tile BM x BN over K-chunk, 256 threads,
// per-thread 8x8 micro-tile computed as 4x8 f32x2 pairs (paired along M).
// A-pairs come directly from the transposed As tile (ulonglong2 loads);
// b values are broadcast-packed on the ALU pipe (does not contend with fma).
__global__ void __launch_bounds__(256, 1) gemm_tile(
    const float* __restrict__ A, const float* __restrict__ B,
    float* __restrict__ C, int lda, int ldb, int ldc,
    long zstride, int kchunk)
{
    __shared__ __align__(16) float As[2][BK][BM];   // transposed A tile
    __shared__ __align__(16) float Bs[2][BK][BN];

    const int tid = threadIdx.x;
    const int tr = tid >> 3;          // 0..31 (row group)
    const int tc = tid & 7;           // 0..7  (col group)
    const int row0 = blockIdx.x * BM;
    const int col0 = blockIdx.y * BN;
    const int k0 = blockIdx.z * kchunk;

    // A-tile load mapping
    const int lr = tid >> 2;          // 0..63
    const int lc = (tid & 3) * 4;     // 0,4,8,12
    // B-tile load mapping
    const int brow = tid >> 4;        // 0..15
    const int bcol = (tid & 15) * 4;  // 0..60

    const float* Abase = A + (size_t)(row0 + lr) * lda + lc;
    const float* Bbase = B + (size_t)brow * ldb + col0 + bcol;

    u64 acc[4][8];                    // acc[ii][j] = {C[2ii][j], C[2ii+1][j]}
    #pragma unroll
    for (int i = 0; i < 4; i++)
        #pragma unroll
        for (int j = 0; j < 8; j++) acc[i][j] = 0ull;

    const int ntiles = kchunk / BK;

    float4 av[4];
    float4 bv;
    // preload tile 0
    {
        const float* Ap = Abase + k0;
        #pragma unroll
        for (int p = 0; p < 4; p++)
            av[p] = *reinterpret_cast<const float4*>(Ap + (size_t)(p * 64) * lda);
        bv = *reinterpret_cast<const float4*>(Bbase + (size_t)k0 * ldb);
    }
    #pragma unroll
    for (int p = 0; p < 4; p++) {
        As[0][lc + 0][p * 64 + lr] = av[p].x;
        As[0][lc + 1][p * 64 + lr] = av[p].y;
        As[0][lc + 2][p * 64 + lr] = av[p].z;
        As[0][lc + 3][p * 64 + lr] = av[p].w;
    }
    *reinterpret_cast<float4*>(&Bs[0][brow][bcol]) = bv;
    __syncthreads();

    int buf = 0;
    for (int kt = 0; kt < ntiles; kt++) {
        const bool has_next = (kt + 1 < ntiles);
        if (has_next) {
            const int kk = k0 + (kt + 1) * BK;
            const float* Ap = Abase + kk;
            #pragma unroll
            for (int p = 0; p < 4; p++)
                av[p] = *reinterpret_cast<const float4*>(Ap + (size_t)(p * 64) * lda);
            bv = *reinterpret_cast<const float4*>(Bbase + (size_t)kk * ldb);
        }
        #pragma unroll
        for (int k = 0; k < BK; k++) {
            ulonglong2 A0 = *reinterpret_cast<const ulonglong2*>(&As[buf][k][tr * 8]);
            ulonglong2 A1 = *reinterpret_cast<const ulonglong2*>(&As[buf][k][tr * 8 + 4]);
            float4 b0 = *reinterpret_cast<const float4*>(&Bs[buf][k][tc * 8]);
            float4 b1 = *reinterpret_cast<const float4*>(&Bs[buf][k][tc * 8 + 4]);
            u64 ar[4];
            ar[0] = A0.x; ar[1] = A0.y; ar[2] = A1.x; ar[3] = A1.y;
            u64 bb[8];
            bb[0] = pack2(b0.x, b0.x);
            bb[1] = pack2(b0.y, b0.y);
            bb[2] = pack2(b0.z, b0.z);
            bb[3] = pack2(b0.w, b0.w);
            bb[4] = pack2(b1.x, b1.x);
            bb[5] = pack2(b1.y, b1.y);
            bb[6] = pack2(b1.z, b1.z);
            bb[7] = pack2(b1.w, b1.w);
            #pragma unroll
            for (int ii = 0; ii < 4; ii++)
                #pragma unroll
                for (int j = 0; j < 8; j++)
                    ffma2(acc[ii][j], ar[ii], bb[j]);
        }
        if (has_next) {
            const int nb = buf ^ 1;
            #pragma unroll
            for (int p = 0; p < 4; p++) {
                As[nb][lc + 0][p * 64 + lr] = av[p].x;
                As[nb][lc + 1][p * 64 + lr] = av[p].y;
                As[nb][lc + 2][p * 64 + lr] = av[p].z;
                As[nb][lc + 3][p * 64 + lr] = av[p].w;
            }
            *reinterpret_cast<float4*>(&Bs[nb][brow][bcol]) = bv;
        }
        __syncthreads();
        buf ^= 1;
    }

    float* Cp = C + (size_t)blockIdx.z * zstride + (size_t)(row0 + tr * 8) * ldc + col0 + tc * 8;
    #pragma unroll
    for (int ii = 0; ii < 4; ii++) {
        float lo[8], hi[8];
        #pragma unroll
        for (int j = 0; j < 8; j++) unpack2(acc[ii][j], lo[j], hi[j]);
        float* r0 = Cp + (size_t)(2 * ii) * ldc;
        float* r1 = Cp + (size_t)(2 * ii + 1) * ldc;
        *reinterpret_cast<float4*>(r0)     = make_float4(lo[0], lo[1], lo[2], lo[3]);
        *reinterpret_cast<float4*>(r0 + 4) = make_float4(lo[4], lo[5], lo[6], lo[7]);
        *reinterpret_cast<float4*>(r1)     = make_float4(hi[0], hi[1], hi[2], hi[3]);
        *reinterpret_cast<float4*>(r1 + 4) = make_float4(hi[4], hi[5], hi[6], hi[7]);
    }
}

// ---------------- gates + LSTM update ---------------------------------------
// Reduces the KSPLIT partials, applies U, LSTM nonlinearity, writes new h,c.
#define GROWS 16
__global__ void __launch_bounds__(128) gates_kernel(int t) {
    const int tid = threadIdx.x;      // gate column j = tid
    __shared__ float sv[101];
    __shared__ float sg[128];

    float uj[101];                    // U column j, register-resident
    #pragma unroll
    for (int k = 0; k < 101; k++) uj[k] = g_U[k * 128 + tid];
    const float bj = g_bias[tid];

    const int row_base = blockIdx.x * GROWS;
    for (int r = 0; r < GROWS; r++) {
        const int n = row_base + r;
        if (tid < 64) {               // reduce A@[h|c] partials
            float s = 0.f;
            #pragma unroll
            for (int z = 0; z < KSPLIT; z++)
                s += g_Mpart[((size_t)z * NN + n) * 64 + tid];
            sv[tid] = s;
        } else if (tid < 96) {        // old h
            sv[tid] = g_HC[n * 64 + (tid - 64)];
        } else if (tid < 101) {       // (A@x_t) row
            sv[tid] = g_C1[(size_t)n * 1024 + t * FIN + (tid - 96)];
        }
        __syncthreads();

        float g = bj;
        #pragma unroll
        for (int k = 0; k < 101; k++) g += sv[k] * uj[k];
        sg[tid] = g;
        __syncthreads();

        if (tid < 32) {
            float ii = 1.f / (1.f + expf(-sg[tid]));
            float ff = 1.f / (1.f + expf(-sg[32 + tid]));
            float gg = tanhf(sg[64 + tid]);
            float oo = 1.f / (1.f + expf(-sg[96 + tid]));
            float c_old = g_HC[n * 64 + 32 + tid];
            float c_new = ff * c_old + ii * gg;
            g_HC[n * 64 + tid] = oo * tanhf(c_new);
            g_HC[n * 64 + 32 + tid] = c_new;
        }
        __syncthreads();
    }
}

// ---------------- final projection ------------------------------------------
__global__ void final_kernel(const float* __restrict__ W_fc,
                             const float* __restrict__ b_fc,
                             float* __restrict__ out) {
    int n = blockIdx.x * blockDim.x + threadIdx.x;
    if (n >= NN) return;
    float s = b_fc[0];
    #pragma unroll
    for (int u = 0; u < HDIM; u++) s += g_HC[n * 64 + u] * W_fc[u];
    out[n] = s;
}

// ---------------- launch ------------------------------------------------------
extern "C" void kernel_launch(void* const* d_in, const int* in_sizes, int n_in,
                              void* d_out, int out_size) {
    const float* X    = (const float*)d_in[0];
    const float* A    = (const float*)d_in[1];
    const float* Wx   = (const float*)d_in[2];
    const float* Wh   = (const float*)d_in[3];
    const float* Wc   = (const float*)d_in[4];
    const float* W_ih = (const float*)d_in[5];
    const float* W_hh = (const float*)d_in[6];
    const float* b_ih = (const float*)d_in[7];
    const float* b_hh = (const float*)d_in[8];
    const float* W_fc = (const float*)d_in[9];
    const float* b_fc = (const float*)d_in[10];

    float *dXr, *dC1, *dHC, *dMp;
    cudaGetSymbolAddress((void**)&dXr, g_Xr);
    cudaGetSymbolAddress((void**)&dC1, g_C1);
    cudaGetSymbolAddress((void**)&dHC, g_HC);
    cudaGetSymbolAddress((void**)&dMp, g_Mpart);

    setup_kernel<<<1, 128>>>(Wx, Wh, Wc, W_ih, W_hh, b_ih, b_hh);
    zero_hc_kernel<<<(NN * 64 + 255) / 256, 256>>>();
    xr_kernel<<<(NN * 1024) / 256, 256>>>(X);

    // one-time precompute: C1 = A @ Xr  ([4096x4096]@[4096x1024])
    gemm_tile<<<dim3(NN / BM, 1024 / BN, 1), 256>>>(A, dXr, dC1,
                                                    NN, 1024, 1024, 0L, NN);

    for (int t = 0; t < TROLL; t++) {
        // M = A @ [h|c], K-split into 8 partials (128 blocks ~ one full wave)
        gemm_tile<<<dim3(NN / BM, 1, KSPLIT), 256>>>(A, dHC, dMp,
                                                     NN, 64, 64,
                                                     (long)NN * 64, KCHUNK);
        gates_kernel<<<NN / GROWS, 128>>>(t);
    }

    final_kernel<<<NN / 256, 256>>>(W_fc, b_fc, (float*)d_out);
}

// round 6
// speedup vs baseline: 1.0029x; 1.0029x over previous
#include <cuda_runtime.h>
#include <math.h>

// Problem constants
#define NN    4096      // nodes
#define HDIM  32
#define TROLL 200
#define FIN   5
#define KSPLIT 8        // K-split factor for per-step GEMM
#define KCHUNK (NN / KSPLIT)   // 512

// GEMM tile config
#define BM 256
#define BN 64
#define BK 16

typedef unsigned long long u64;

__device__ __forceinline__ u64 pack2(float x, float y) {
    u64 r;
    asm("mov.b64 %0, {%1, %2};" : "=l"(r) : "f"(x), "f"(y));
    return r;
}
__device__ __forceinline__ void unpack2(u64 v, float& x, float& y) {
    asm("mov.b64 {%0, %1}, %2;" : "=f"(x), "=f"(y) : "l"(v));
}
__device__ __forceinline__ void ffma2(u64& d, u64 a, u64 b) {
    asm("fma.rn.f32x2 %0, %1, %2, %0;" : "+l"(d) : "l"(a), "l"(b));
}

// ---------------- device scratch (allocation-free: __device__ globals) ------
__device__ __align__(16) float g_HC[NN * 64];               // [n][0:32]=h, [32:64]=c
__device__ __align__(16) float g_Mpart[(size_t)KSPLIT * NN * 64]; // K-split partials of A@[h|c]
__device__ __align__(16) float g_Xr[(size_t)NN * 1024];     // X rearranged [k][t*5+f], padded to 1024
__device__ __align__(16) float g_C1[(size_t)NN * 1024];     // A @ Xr
__device__ __align__(16) float g_U[101 * 128];              // fused gate matrix
__device__ __align__(16) float g_bias[128];                 // b_ih + b_hh

// ---------------- setup: build fused gate matrix U --------------------------
// gates[n,j] = bias[j] + sum_k v[n,k] * U[k,j]
//   v = [ (A@h)[0:32] | (A@c)[0:32] | h[0:32] | (A@x_t)[0:5] ]
__global__ void setup_kernel(const float* __restrict__ Wx, const float* __restrict__ Wh,
                             const float* __restrict__ Wc, const float* __restrict__ W_ih,
                             const float* __restrict__ W_hh, const float* __restrict__ b_ih,
                             const float* __restrict__ b_hh) {
    const int j = threadIdx.x;  // 0..127 gate column
    __shared__ float sWih[128 * 32];
    for (int i = j; i < 128 * 32; i += 128) sWih[i] = W_ih[i];
    __syncthreads();

    for (int r = 0; r < 32; r++) {
        float s = 0.f;
        for (int m = 0; m < 32; m++) s += Wh[r * 32 + m] * sWih[j * 32 + m];
        g_U[r * 128 + j] = s;
    }
    for (int r = 0; r < 32; r++) {
        float s = 0.f;
        for (int m = 0; m < 32; m++) s += Wc[r * 32 + m] * sWih[j * 32 + m];
        g_U[(32 + r) * 128 + j] = s;
    }
    for (int m = 0; m < 32; m++) g_U[(64 + m) * 128 + j] = W_hh[j * 32 + m];
    for (int f = 0; f < FIN; f++) {
        float s = 0.f;
        for (int m = 0; m < 32; m++) s += Wx[f * 32 + m] * sWih[j * 32 + m];
        g_U[(96 + f) * 128 + j] = s;
    }
    g_bias[j] = b_ih[j] + b_hh[j];
}

__global__ void zero_hc_kernel() {
    int i = blockIdx.x * blockDim.x + threadIdx.x;
    if (i < NN * 64) g_HC[i] = 0.f;
}

// Rearrange X[t][k][f] -> Xr[k][t*5+f], zero-pad cols 1000..1023
__global__ void xr_kernel(const float* __restrict__ X) {
    int idx = blockIdx.x * blockDim.x + threadIdx.x;   // over NN*1024
    int k = idx >> 10;
    int q = idx & 1023;
    float v = 0.f;
    if (q < TROLL * FIN) {
        int t = q / FIN;
        int f = q - t * FIN;
        v = X[(size_t)t * (NN * FIN) + k * FIN + f];
    }
    g_Xr[idx] = v;
}

// ---------------- tiled fp32 GEMM with packed FFMA2 --------------------------
// C[z] = A[rows, krange] @ B. Block tile BM x BN over K-chunk, 256 threads,
// per-thread 8x8 micro-tile computed as 4x8 f32x2 pairs (paired along M).
// A-pairs come directly from the transposed As tile (ulonglong2 loads);
// b values are broadcast-packed on the ALU pipe (does not contend with fma).
__global__ void __launch_bounds__(256, 1) gemm_tile(
    const float* __restrict__ A, const float* __restrict__ B,
    float* __restrict__ C, int lda, int ldb, int ldc,
    long zstride, int kchunk)
{
    __shared__ __align__(16) float As[2][BK][BM];   // transposed A tile
    __shared__ __align__(16) float Bs[2][BK][BN];

    const int tid = threadIdx.x;
    const int tr = tid >> 3;          // 0..31 (row group)
    const int tc = tid & 7;           // 0..7  (col group)
    const int row0 = blockIdx.x * BM;
    const int col0 = blockIdx.y * BN;
    const int k0 = blockIdx.z * kchunk;

    // A-tile load mapping
    const int lr = tid >> 2;          // 0..63
    const int lc = (tid & 3) * 4;     // 0,4,8,12
    // B-tile load mapping
    const int brow = tid >> 4;        // 0..15
    const int bcol = (tid & 15) * 4;  // 0..60

    const float* Abase = A + (size_t)(row0 + lr) * lda + lc;
    const float* Bbase = B + (size_t)brow * ldb + col0 + bcol;

    u64 acc[4][8];                    // acc[ii][j] = {C[2ii][j], C[2ii+1][j]}
    #pragma unroll
    for (int i = 0; i < 4; i++)
        #pragma unroll
        for (int j = 0; j < 8; j++) acc[i][j] = 0ull;

    const int ntiles = kchunk / BK;

    float4 av[4];
    float4 bv;
    // preload tile 0
    {
        const float* Ap = Abase + k0;
        #pragma unroll
        for (int p = 0; p < 4; p++)
            av[p] = *reinterpret_cast<const float4*>(Ap + (size_t)(p * 64) * lda);
        bv = *reinterpret_cast<const float4*>(Bbase + (size_t)k0 * ldb);
    }
    #pragma unroll
    for (int p = 0; p < 4; p++) {
        As[0][lc + 0][p * 64 + lr] = av[p].x;
        As[0][lc + 1][p * 64 + lr] = av[p].y;
        As[0][lc + 2][p * 64 + lr] = av[p].z;
        As[0][lc + 3][p * 64 + lr] = av[p].w;
    }
    *reinterpret_cast<float4*>(&Bs[0][brow][bcol]) = bv;
    __syncthreads();

    int buf = 0;
    for (int kt = 0; kt < ntiles; kt++) {
        const bool has_next = (kt + 1 < ntiles);
        if (has_next) {
            const int kk = k0 + (kt + 1) * BK;
            const float* Ap = Abase + kk;
            #pragma unroll
            for (int p = 0; p < 4; p++)
                av[p] = *reinterpret_cast<const float4*>(Ap + (size_t)(p * 64) * lda);
            bv = *reinterpret_cast<const float4*>(Bbase + (size_t)kk * ldb);
        }
        #pragma unroll
        for (int k = 0; k < BK; k++) {
            ulonglong2 A0 = *reinterpret_cast<const ulonglong2*>(&As[buf][k][tr * 8]);
            ulonglong2 A1 = *reinterpret_cast<const ulonglong2*>(&As[buf][k][tr * 8 + 4]);
            float4 b0 = *reinterpret_cast<const float4*>(&Bs[buf][k][tc * 8]);
            float4 b1 = *reinterpret_cast<const float4*>(&Bs[buf][k][tc * 8 + 4]);
            u64 ar[4];
            ar[0] = A0.x; ar[1] = A0.y; ar[2] = A1.x; ar[3] = A1.y;
            u64 bb[8];
            bb[0] = pack2(b0.x, b0.x);
            bb[1] = pack2(b0.y, b0.y);
            bb[2] = pack2(b0.z, b0.z);
            bb[3] = pack2(b0.w, b0.w);
            bb[4] = pack2(b1.x, b1.x);
            bb[5] = pack2(b1.y, b1.y);
            bb[6] = pack2(b1.z, b1.z);
            bb[7] = pack2(b1.w, b1.w);
            #pragma unroll
            for (int ii = 0; ii < 4; ii++)
                #pragma unroll
                for (int j = 0; j < 8; j++)
                    ffma2(acc[ii][j], ar[ii], bb[j]);
        }
        if (has_next) {
            const int nb = buf ^ 1;
            #pragma unroll
            for (int p = 0; p < 4; p++) {
                As[nb][lc + 0][p * 64 + lr] = av[p].x;
                As[nb][lc + 1][p * 64 + lr] = av[p].y;
                As[nb][lc + 2][p * 64 + lr] = av[p].z;
                As[nb][lc + 3][p * 64 + lr] = av[p].w;
            }
            *reinterpret_cast<float4*>(&Bs[nb][brow][bcol]) = bv;
        }
        __syncthreads();
        buf ^= 1;
    }

    float* Cp = C + (size_t)blockIdx.z * zstride + (size_t)(row0 + tr * 8) * ldc + col0 + tc * 8;
    #pragma unroll
    for (int ii = 0; ii < 4; ii++) {
        float lo[8], hi[8];
        #pragma unroll
        for (int j = 0; j < 8; j++) unpack2(acc[ii][j], lo[j], hi[j]);
        float* r0 = Cp + (size_t)(2 * ii) * ldc;
        float* r1 = Cp + (size_t)(2 * ii + 1) * ldc;
        *reinterpret_cast<float4*>(r0)     = make_float4(lo[0], lo[1], lo[2], lo[3]);
        *reinterpret_cast<float4*>(r0 + 4) = make_float4(lo[4], lo[5], lo[6], lo[7]);
        *reinterpret_cast<float4*>(r1)     = make_float4(hi[0], hi[1], hi[2], hi[3]);
        *reinterpret_cast<float4*>(r1 + 4) = make_float4(hi[4], hi[5], hi[6], hi[7]);
    }
}

// ---------------- gates + LSTM update ---------------------------------------
// Reduces the KSPLIT partials, applies U, LSTM nonlinearity, writes new h,c.
#define GROWS 16
__global__ void __launch_bounds__(128) gates_kernel(int t) {
    const int tid = threadIdx.x;      // gate column j = tid
    __shared__ float sv[101];
    __shared__ float sg[128];

    float uj[101];                    // U column j, register-resident
    #pragma unroll
    for (int k = 0; k < 101; k++) uj[k] = g_U[k * 128 + tid];
    const float bj = g_bias[tid];

    const int row_base = blockIdx.x * GROWS;
    for (int r = 0; r < GROWS; r++) {
        const int n = row_base + r;
        if (tid < 64) {               // reduce A@[h|c] partials
            float s = 0.f;
            #pragma unroll
            for (int z = 0; z < KSPLIT; z++)
                s += g_Mpart[((size_t)z * NN + n) * 64 + tid];
            sv[tid] = s;
        } else if (tid < 96) {        // old h
            sv[tid] = g_HC[n * 64 + (tid - 64)];
        } else if (tid < 101) {       // (A@x_t) row
            sv[tid] = g_C1[(size_t)n * 1024 + t * FIN + (tid - 96)];
        }
        __syncthreads();

        float g = bj;
        #pragma unroll
        for (int k = 0; k < 101; k++) g += sv[k] * uj[k];
        sg[tid] = g;
        __syncthreads();

        if (tid < 32) {
            float ii = 1.f / (1.f + expf(-sg[tid]));
            float ff = 1.f / (1.f + expf(-sg[32 + tid]));
            float gg = tanhf(sg[64 + tid]);
            float oo = 1.f / (1.f + expf(-sg[96 + tid]));
            float c_old = g_HC[n * 64 + 32 + tid];
            float c_new = ff * c_old + ii * gg;
            g_HC[n * 64 + tid] = oo * tanhf(c_new);
            g_HC[n * 64 + 32 + tid] = c_new;
        }
        __syncthreads();
    }
}

// ---------------- final projection ------------------------------------------
__global__ void final_kernel(const float* __restrict__ W_fc,
                             const float* __restrict__ b_fc,
                             float* __restrict__ out) {
    int n = blockIdx.x * blockDim.x + threadIdx.x;
    if (n >= NN) return;
    float s = b_fc[0];
    #pragma unroll
    for (int u = 0; u < HDIM; u++) s += g_HC[n * 64 + u] * W_fc[u];
    out[n] = s;
}

// ---------------- launch ------------------------------------------------------
extern "C" void kernel_launch(void* const* d_in, const int* in_sizes, int n_in,
                              void* d_out, int out_size) {
    const float* X    = (const float*)d_in[0];
    const float* A    = (const float*)d_in[1];
    const float* Wx   = (const float*)d_in[2];
    const float* Wh   = (const float*)d_in[3];
    const float* Wc   = (const float*)d_in[4];
    const float* W_ih = (const float*)d_in[5];
    const float* W_hh = (const float*)d_in[6];
    const float* b_ih = (const float*)d_in[7];
    const float* b_hh = (const float*)d_in[8];
    const float* W_fc = (const float*)d_in[9];
    const float* b_fc = (const float*)d_in[10];

    float *dXr, *dC1, *dHC, *dMp;
    cudaGetSymbolAddress((void**)&dXr, g_Xr);
    cudaGetSymbolAddress((void**)&dC1, g_C1);
    cudaGetSymbolAddress((void**)&dHC, g_HC);
    cudaGetSymbolAddress((void**)&dMp, g_Mpart);

    setup_kernel<<<1, 128>>>(Wx, Wh, Wc, W_ih, W_hh, b_ih, b_hh);
    zero_hc_kernel<<<(NN * 64 + 255) / 256, 256>>>();
    xr_kernel<<<(NN * 1024) / 256, 256>>>(X);

    // one-time precompute: C1 = A @ Xr  ([4096x4096]@[4096x1024])
    gemm_tile<<<dim3(NN / BM, 1024 / BN, 1), 256>>>(A, dXr, dC1,
                                                    NN, 1024, 1024, 0L, NN);

    for (int t = 0; t < TROLL; t++) {
        // M = A @ [h|c], K-split into 8 partials (128 blocks ~ one full wave)
        gemm_tile<<<dim3(NN / BM, 1, KSPLIT), 256>>>(A, dHC, dMp,
                                                     NN, 64, 64,
                                                     (long)NN * 64, KCHUNK);
        gates_kernel<<<NN / GROWS, 128>>>(t);
    }

    final_kernel<<<NN / 256, 256>>>(W_fc, b_fc, (float*)d_out);
}

// round 9
// speedup vs baseline: 1.9399x; 1.9343x over previous
#include <cuda_runtime.h>
#include <cuda_bf16.h>
#include <math.h>
#include <cstdint>

// Problem constants
#define NN    4096
#define HDIM  32
#define TROLL 200
#define FIN   5

#define MSPLIT 4               // K-split; each CTA handles K=1024 (8 tiles of 128)
#define NKT    8               // k-tiles per CTA

// fp32 GEMM (C1 precompute) config
#define BM 256
#define BN 64
#define BK 16

typedef unsigned long long u64;

// ---------------- fp32x2 helpers (C1 precompute GEMM) -----------------------
__device__ __forceinline__ u64 pack2(float x, float y) {
    u64 r; asm("mov.b64 %0, {%1, %2};" : "=l"(r) : "f"(x), "f"(y)); return r;
}
__device__ __forceinline__ void unpack2(u64 v, float& x, float& y) {
    asm("mov.b64 {%0, %1}, %2;" : "=f"(x), "=f"(y) : "l"(v));
}
__device__ __forceinline__ void ffma2(u64& d, u64 a, u64 b) {
    asm("fma.rn.f32x2 %0, %1, %2, %0;" : "+l"(d) : "l"(a), "l"(b));
}

// ---------------- mma.sync helpers (sm_80-class, compiles for compute_103) ---
__device__ __forceinline__ uint32_t smem_u32(const void* p) {
    uint32_t a;
    asm("{ .reg .u64 t; cvta.to.shared.u64 t, %1; cvt.u32.u64 %0, t; }" : "=r"(a) : "l"(p));
    return a;
}
__device__ __forceinline__ void ldm_x4(uint32_t* r, uint32_t addr) {
    asm volatile("ldmatrix.sync.aligned.m8n8.x4.shared.b16 {%0,%1,%2,%3}, [%4];"
        : "=r"(r[0]), "=r"(r[1]), "=r"(r[2]), "=r"(r[3]) : "r"(addr));
}
__device__ __forceinline__ void mma_bf16(float* d, const uint32_t* a, uint32_t b0, uint32_t b1) {
    asm volatile("mma.sync.aligned.m16n8k16.row.col.f32.bf16.bf16.f32 "
        "{%0,%1,%2,%3}, {%4,%5,%6,%7}, {%8,%9}, {%0,%1,%2,%3};"
        : "+f"(d[0]), "+f"(d[1]), "+f"(d[2]), "+f"(d[3])
        : "r"(a[0]), "r"(a[1]), "r"(a[2]), "r"(a[3]), "r"(b0), "r"(b1));
}
__device__ __forceinline__ void cp_async16(uint32_t saddr, const void* gaddr) {
    asm volatile("cp.async.cg.shared.global [%0], [%1], 16;"
        :: "r"(saddr), "l"(gaddr) : "memory");
}
#define CP_COMMIT() asm volatile("cp.async.commit_group;" ::: "memory")

// ---------------- device scratch ---------------------------------------------
__device__ __align__(16) float g_HC[NN * 64];                      // [n][0:32]=h,[32:64]=c
__device__ __align__(16) float g_Mpart[(size_t)MSPLIT * NN * 64];  // K-split partials
__device__ __align__(16) float g_Xr[(size_t)NN * 1024];
__device__ __align__(16) float g_C1[(size_t)NN * 1024];
__device__ __align__(16) float g_U[101 * 128];
__device__ __align__(16) float g_bias[128];
// A split into bf16 hi/lo, ldmatrix-ready 128x128 tiles.
// tile (mt, ktg) at byte offset ((mt*32+ktg) << 15); inside tile:
//   byte(row, k) = row*256 + (((k>>3) ^ (row&7)) << 4) + (k&7)*2
__device__ __align__(16) __nv_bfloat16 g_Ah[(size_t)NN * NN];
__device__ __align__(16) __nv_bfloat16 g_Al[(size_t)NN * NN];
// HC^T (Bt[n][k]) split hi/lo, 64x128 tiles (16KB), tile ktg at (ktg<<14)
__device__ __align__(16) __nv_bfloat16 g_Bh[(size_t)64 * NN];
__device__ __align__(16) __nv_bfloat16 g_Bl[(size_t)64 * NN];

// ---------------- setup: fused gate matrix U ---------------------------------
__global__ void setup_kernel(const float* __restrict__ Wx, const float* __restrict__ Wh,
                             const float* __restrict__ Wc, const float* __restrict__ W_ih,
                             const float* __restrict__ W_hh, const float* __restrict__ b_ih,
                             const float* __restrict__ b_hh) {
    const int j = threadIdx.x;
    __shared__ float sWih[128 * 32];
    for (int i = j; i < 128 * 32; i += 128) sWih[i] = W_ih[i];
    __syncthreads();
    for (int r = 0; r < 32; r++) {
        float s = 0.f;
        for (int m = 0; m < 32; m++) s += Wh[r * 32 + m] * sWih[j * 32 + m];
        g_U[r * 128 + j] = s;
    }
    for (int r = 0; r < 32; r++) {
        float s = 0.f;
        for (int m = 0; m < 32; m++) s += Wc[r * 32 + m] * sWih[j * 32 + m];
        g_U[(32 + r) * 128 + j] = s;
    }
    for (int m = 0; m < 32; m++) g_U[(64 + m) * 128 + j] = W_hh[j * 32 + m];
    for (int f = 0; f < FIN; f++) {
        float s = 0.f;
        for (int m = 0; m < 32; m++) s += Wx[f * 32 + m] * sWih[j * 32 + m];
        g_U[(96 + f) * 128 + j] = s;
    }
    g_bias[j] = b_ih[j] + b_hh[j];
}

__global__ void zero_hc_kernel() {
    int i = blockIdx.x * blockDim.x + threadIdx.x;
    if (i < NN * 64) g_HC[i] = 0.f;
}

__global__ void xr_kernel(const float* __restrict__ X) {
    int idx = blockIdx.x * blockDim.x + threadIdx.x;
    int k = idx >> 10;
    int q = idx & 1023;
    float v = 0.f;
    if (q < TROLL * FIN) {
        int t = q / FIN;
        int f = q - t * FIN;
        v = X[(size_t)t * (NN * FIN) + k * FIN + f];
    }
    g_Xr[idx] = v;
}

// ---------------- A -> bf16 hi/lo ldmatrix-tiled layout (once) ----------------
__global__ void aconv_kernel(const float* __restrict__ A) {
    int idx = blockIdx.x * blockDim.x + threadIdx.x;   // NN*512 threads, 8 elems each
    int r = idx >> 9;
    int k = (idx & 511) << 3;                          // 16B chunk of 8 bf16
    int mt = r >> 7, rin = r & 127;
    int ktg = k >> 7, kin = k & 127;
    uint32_t byte = (uint32_t)(rin * 256 + ((((kin >> 3)) ^ (rin & 7)) << 4));
    size_t tile = ((size_t)(mt * 32 + ktg)) << 15;     // 32KB tiles
    unsigned short h[8], l[8];
    #pragma unroll
    for (int i = 0; i < 8; i++) {
        float x = A[(size_t)r * NN + k + i];
        __nv_bfloat16 bh = __float2bfloat16(x);
        __nv_bfloat16 bl = __float2bfloat16(x - __bfloat162float(bh));
        h[i] = __bfloat16_as_ushort(bh);
        l[i] = __bfloat16_as_ushort(bl);
    }
    uint4 vh = make_uint4((uint32_t)h[0] | ((uint32_t)h[1] << 16),
                          (uint32_t)h[2] | ((uint32_t)h[3] << 16),
                          (uint32_t)h[4] | ((uint32_t)h[5] << 16),
                          (uint32_t)h[6] | ((uint32_t)h[7] << 16));
    uint4 vl = make_uint4((uint32_t)l[0] | ((uint32_t)l[1] << 16),
                          (uint32_t)l[2] | ((uint32_t)l[3] << 16),
                          (uint32_t)l[4] | ((uint32_t)l[5] << 16),
                          (uint32_t)l[6] | ((uint32_t)l[7] << 16));
    *reinterpret_cast<uint4*>(reinterpret_cast<char*>(g_Ah) + tile + byte) = vh;
    *reinterpret_cast<uint4*>(reinterpret_cast<char*>(g_Al) + tile + byte) = vl;
}

// ---------------- HC -> Bt bf16 hi/lo tiles (per step) ------------------------
__global__ void hcconv_kernel() {
    int idx = blockIdx.x * blockDim.x + threadIdx.x;   // 64*512 threads
    int k8 = idx >> 6;                                 // 0..511: which 16B k-chunk
    int n = idx & 63;
    int k = k8 << 3;
    int ktg = k >> 7, kin = k & 127;
    uint32_t byte = (uint32_t)(n * 256 + ((((kin >> 3)) ^ (n & 7)) << 4));
    size_t tile = (size_t)ktg << 14;                   // 16KB tiles
    unsigned short h[8], l[8];
    #pragma unroll
    for (int i = 0; i < 8; i++) {
        float x = g_HC[(size_t)(k + i) * 64 + n];
        __nv_bfloat16 bh = __float2bfloat16(x);
        __nv_bfloat16 bl = __float2bfloat16(x - __bfloat162float(bh));
        h[i] = __bfloat16_as_ushort(bh);
        l[i] = __bfloat16_as_ushort(bl);
    }
    uint4 vh = make_uint4((uint32_t)h[0] | ((uint32_t)h[1] << 16),
                          (uint32_t)h[2] | ((uint32_t)h[3] << 16),
                          (uint32_t)h[4] | ((uint32_t)h[5] << 16),
                          (uint32_t)h[6] | ((uint32_t)h[7] << 16));
    uint4 vl = make_uint4((uint32_t)l[0] | ((uint32_t)l[1] << 16),
                          (uint32_t)l[2] | ((uint32_t)l[3] << 16),
                          (uint32_t)l[4] | ((uint32_t)l[5] << 16),
                          (uint32_t)l[6] | ((uint32_t)l[7] << 16));
    *reinterpret_cast<uint4*>(reinterpret_cast<char*>(g_Bh) + tile + byte) = vh;
    *reinterpret_cast<uint4*>(reinterpret_cast<char*>(g_Bl) + tile + byte) = vl;
}

// ---------------- step GEMM via mma.sync (HMMA path) --------------------------
// Mpart[z] = A[mt-block, z-kchunk] @ HC[z-kchunk, :]
// grid (32, MSPLIT), 256 threads = 8 warps (4m x 2n), warp tile 32x32.
// Split-precision: acc += Ah*Bh + Ah*Bl + Al*Bh.
// SMEM buffer layout (per stage): Ah 32K | Al 32K | Bh 16K | Bl 16K = 96KB
#define STG_SZ 98304
#define SM_AL  32768
#define SM_BH  65536
#define SM_BL  81920

__global__ void __launch_bounds__(256, 1) step_mma() {
    extern __shared__ __align__(16) char smem[];       // 2 * STG_SZ
    const int tid  = threadIdx.x;
    const int lane = tid & 31;
    const int wid  = tid >> 5;
    const int wm   = wid & 3;          // m-block (32 rows)
    const int wn   = wid >> 2;         // n-block (32 cols)
    const int mt   = blockIdx.x;
    const int z    = blockIdx.y;

    const uint32_t sbase = smem_u32(smem);

    // ---- tile prefetch (cp.async, 16B per op) ----
    auto load_tile = [&](int kt, int b) {
        const int ktg = z * NKT + kt;
        const char* gAh = reinterpret_cast<const char*>(g_Ah) + (((size_t)(mt * 32 + ktg)) << 15);
        const char* gAl = reinterpret_cast<const char*>(g_Al) + (((size_t)(mt * 32 + ktg)) << 15);
        const char* gBh = reinterpret_cast<const char*>(g_Bh) + ((size_t)ktg << 14);
        const char* gBl = reinterpret_cast<const char*>(g_Bl) + ((size_t)ktg << 14);
        const uint32_t s = sbase + b * STG_SZ;
        #pragma unroll
        for (int i = 0; i < 8; i++)
            cp_async16(s + (tid + i * 256) * 16, gAh + (tid + i * 256) * 16);
        #pragma unroll
        for (int i = 0; i < 8; i++)
            cp_async16(s + SM_AL + (tid + i * 256) * 16, gAl + (tid + i * 256) * 16);
        #pragma unroll
        for (int i = 0; i < 4; i++)
            cp_async16(s + SM_BH + (tid + i * 256) * 16, gBh + (tid + i * 256) * 16);
        #pragma unroll
        for (int i = 0; i < 4; i++)
            cp_async16(s + SM_BL + (tid + i * 256) * 16, gBl + (tid + i * 256) * 16);
        CP_COMMIT();
    };

    float acc[2][4][4];
    #pragma unroll
    for (int im = 0; im < 2; im++)
        #pragma unroll
        for (int jn = 0; jn < 4; jn++)
            #pragma unroll
            for (int q = 0; q < 4; q++) acc[im][jn][q] = 0.f;

    load_tile(0, 0);
    load_tile(1, 1);

    // precomputed ldmatrix lane-address components
    const int arow[2] = { wm * 32 + (lane & 15), wm * 32 + 16 + (lane & 15) };
    const int acolh   = (lane >> 4);            // extra k-chunk (0/1)
    const int nrow[2] = { wn * 32 + (lane & 7) + ((lane >> 4) << 3),
                          wn * 32 + 16 + (lane & 7) + ((lane >> 4) << 3) };
    const int bcolh   = (lane >> 3) & 1;

    #pragma unroll
    for (int kt = 0; kt < NKT; kt++) {
        const int b = kt & 1;
        if (kt == NKT - 1) asm volatile("cp.async.wait_group 0;" ::: "memory");
        else               asm volatile("cp.async.wait_group 1;" ::: "memory");
        __syncthreads();

        const uint32_t sA  = sbase + b * STG_SZ;
        const uint32_t sAl_ = sA + SM_AL;
        const uint32_t sBh_ = sA + SM_BH;
        const uint32_t sBl_ = sA + SM_BL;

        #pragma unroll
        for (int ks = 0; ks < 8; ks++) {
            const int ck = ks * 2;
            uint32_t ah[2][4], al[2][4], bh[2][4], bl[2][4];
            #pragma unroll
            for (int im = 0; im < 2; im++) {
                const int r = arow[im];
                const uint32_t off = (uint32_t)(r * 256 + (((ck + acolh) ^ (r & 7)) << 4));
                ldm_x4(ah[im], sA  + off);
                ldm_x4(al[im], sAl_ + off);
            }
            #pragma unroll
            for (int g = 0; g < 2; g++) {
                const int r = nrow[g];
                const uint32_t off = (uint32_t)(r * 256 + (((ck + bcolh) ^ (r & 7)) << 4));
                ldm_x4(bh[g], sBh_ + off);
                ldm_x4(bl[g], sBl_ + off);
            }
            #pragma unroll
            for (int im = 0; im < 2; im++)
                #pragma unroll
                for (int jn = 0; jn < 4; jn++) {
                    const int g = jn >> 1, w = (jn & 1) * 2;
                    mma_bf16(acc[im][jn], ah[im], bh[g][w], bh[g][w + 1]);
                    mma_bf16(acc[im][jn], ah[im], bl[g][w], bl[g][w + 1]);
                    mma_bf16(acc[im][jn], al[im], bh[g][w], bh[g][w + 1]);
                }
        }
        __syncthreads();
        if (kt + 2 < NKT) load_tile(kt + 2, b);
    }

    // ---- epilogue: write 32x32 warp tile to Mpart[z] ----
    float* base = g_Mpart + (size_t)z * NN * 64;
    const int row0 = mt * 128 + wm * 32 + (lane >> 2);
    const int col0 = wn * 32 + (lane & 3) * 2;
    #pragma unroll
    for (int im = 0; im < 2; im++)
        #pragma unroll
        for (int jn = 0; jn < 4; jn++) {
            const int r = row0 + im * 16;
            const int c = col0 + jn * 8;
            *reinterpret_cast<float2*>(&base[(size_t)r * 64 + c]) =
                make_float2(acc[im][jn][0], acc[im][jn][1]);
            *reinterpret_cast<float2*>(&base[(size_t)(r + 8) * 64 + c]) =
                make_float2(acc[im][jn][2], acc[im][jn][3]);
        }
}

// ---------------- fp32 GEMM with FFMA2 (C1 precompute only) -------------------
__global__ void __launch_bounds__(256, 1) gemm_tile(
    const float* __restrict__ A, const float* __restrict__ B,
    float* __restrict__ C, int lda, int ldb, int ldc,
    long zstride, int kchunk)
{
    __shared__ __align__(16) float As[2][BK][BM];
    __shared__ __align__(16) float Bs[2][BK][BN];
    const int tid = threadIdx.x;
    const int tr = tid >> 3, tc = tid & 7;
    const int row0 = blockIdx.x * BM, col0 = blockIdx.y * BN;
    const int k0 = blockIdx.z * kchunk;
    const int lr = tid >> 2, lc = (tid & 3) * 4;
    const int brow = tid >> 4, bcol = (tid & 15) * 4;
    const float* Abase = A + (size_t)(row0 + lr) * lda + lc;
    const float* Bbase = B + (size_t)brow * ldb + col0 + bcol;

    u64 acc[4][8];
    #pragma unroll
    for (int i = 0; i < 4; i++)
        #pragma unroll
        for (int j = 0; j < 8; j++) acc[i][j] = 0ull;

    const int ntiles = kchunk / BK;
    float4 av[4]; float4 bv;
    {
        const float* Ap = Abase + k0;
        #pragma unroll
        for (int p = 0; p < 4; p++)
            av[p] = *reinterpret_cast<const float4*>(Ap + (size_t)(p * 64) * lda);
        bv = *reinterpret_cast<const float4*>(Bbase + (size_t)k0 * ldb);
    }
    #pragma unroll
    for (int p = 0; p < 4; p++) {
        As[0][lc + 0][p * 64 + lr] = av[p].x;
        As[0][lc + 1][p * 64 + lr] = av[p].y;
        As[0][lc + 2][p * 64 + lr] = av[p].z;
        As[0][lc + 3][p * 64 + lr] = av[p].w;
    }
    *reinterpret_cast<float4*>(&Bs[0][brow][bcol]) = bv;
    __syncthreads();

    int buf = 0;
    for (int kt = 0; kt < ntiles; kt++) {
        const bool has_next = (kt + 1 < ntiles);
        if (has_next) {
            const int kk = k0 + (kt + 1) * BK;
            const float* Ap = Abase + kk;
            #pragma unroll
            for (int p = 0; p < 4; p++)
                av[p] = *reinterpret_cast<const float4*>(Ap + (size_t)(p * 64) * lda);
            bv = *reinterpret_cast<const float4*>(Bbase + (size_t)kk * ldb);
        }
        #pragma unroll
        for (int k = 0; k < BK; k++) {
            ulonglong2 A0 = *reinterpret_cast<const ulonglong2*>(&As[buf][k][tr * 8]);
            ulonglong2 A1 = *reinterpret_cast<const ulonglong2*>(&As[buf][k][tr * 8 + 4]);
            float4 b0 = *reinterpret_cast<const float4*>(&Bs[buf][k][tc * 8]);
            float4 b1 = *reinterpret_cast<const float4*>(&Bs[buf][k][tc * 8 + 4]);
            u64 ar[4] = {A0.x, A0.y, A1.x, A1.y};
            u64 bb[8] = {pack2(b0.x, b0.x), pack2(b0.y, b0.y), pack2(b0.z, b0.z), pack2(b0.w, b0.w),
                         pack2(b1.x, b1.x), pack2(b1.y, b1.y), pack2(b1.z, b1.z), pack2(b1.w, b1.w)};
            #pragma unroll
            for (int ii = 0; ii < 4; ii++)
                #pragma unroll
                for (int j = 0; j < 8; j++)
                    ffma2(acc[ii][j], ar[ii], bb[j]);
        }
        if (has_next) {
            const int nb = buf ^ 1;
            #pragma unroll
            for (int p = 0; p < 4; p++) {
                As[nb][lc + 0][p * 64 + lr] = av[p].x;
                As[nb][lc + 1][p * 64 + lr] = av[p].y;
                As[nb][lc + 2][p * 64 + lr] = av[p].z;
                As[nb][lc + 3][p * 64 + lr] = av[p].w;
            }
            *reinterpret_cast<float4*>(&Bs[nb][brow][bcol]) = bv;
        }
        __syncthreads();
        buf ^= 1;
    }

    float* Cp = C + (size_t)blockIdx.z * zstride + (size_t)(row0 + tr * 8) * ldc + col0 + tc * 8;
    #pragma unroll
    for (int ii = 0; ii < 4; ii++) {
        float lo[8], hi[8];
        #pragma unroll
        for (int j = 0; j < 8; j++) unpack2(acc[ii][j], lo[j], hi[j]);
        float* r0 = Cp + (size_t)(2 * ii) * ldc;
        float* r1 = Cp + (size_t)(2 * ii + 1) * ldc;
        *reinterpret_cast<float4*>(r0)     = make_float4(lo[0], lo[1], lo[2], lo[3]);
        *reinterpret_cast<float4*>(r0 + 4) = make_float4(lo[4], lo[5], lo[6], lo[7]);
        *reinterpret_cast<float4*>(r1)     = make_float4(hi[0], hi[1], hi[2], hi[3]);
        *reinterpret_cast<float4*>(r1 + 4) = make_float4(hi[4], hi[5], hi[6], hi[7]);
    }
}

// ---------------- gates + LSTM update -----------------------------------------
#define GROWS 16
__global__ void __launch_bounds__(128) gates_kernel(int t) {
    const int tid = threadIdx.x;
    __shared__ float sv[101];
    __shared__ float sg[128];

    float uj[101];
    #pragma unroll
    for (int k = 0; k < 101; k++) uj[k] = g_U[k * 128 + tid];
    const float bj = g_bias[tid];

    const int row_base = blockIdx.x * GROWS;
    for (int r = 0; r < GROWS; r++) {
        const int n = row_base + r;
        if (tid < 64) {
            float s = 0.f;
            #pragma unroll
            for (int zz = 0; zz < MSPLIT; zz++)
                s += g_Mpart[((size_t)zz * NN + n) * 64 + tid];
            sv[tid] = s;
        } else if (tid < 96) {
            sv[tid] = g_HC[n * 64 + (tid - 64)];
        } else if (tid < 101) {
            sv[tid] = g_C1[(size_t)n * 1024 + t * FIN + (tid - 96)];
        }
        __syncthreads();

        float g = bj;
        #pragma unroll
        for (int k = 0; k < 101; k++) g += sv[k] * uj[k];
        sg[tid] = g;
        __syncthreads();

        if (tid < 32) {
            float ii = 1.f / (1.f + expf(-sg[tid]));
            float ff = 1.f / (1.f + expf(-sg[32 + tid]));
            float gg = tanhf(sg[64 + tid]);
            float oo = 1.f / (1.f + expf(-sg[96 + tid]));
            float c_old = g_HC[n * 64 + 32 + tid];
            float c_new = ff * c_old + ii * gg;
            g_HC[n * 64 + tid] = oo * tanhf(c_new);
            g_HC[n * 64 + 32 + tid] = c_new;
        }
        __syncthreads();
    }
}

// ---------------- final projection --------------------------------------------
__global__ void final_kernel(const float* __restrict__ W_fc,
                             const float* __restrict__ b_fc,
                             float* __restrict__ out) {
    int n = blockIdx.x * blockDim.x + threadIdx.x;
    if (n >= NN) return;
    float s = b_fc[0];
    #pragma unroll
    for (int u = 0; u < HDIM; u++) s += g_HC[n * 64 + u] * W_fc[u];
    out[n] = s;
}

// ---------------- launch --------------------------------------------------------
extern "C" void kernel_launch(void* const* d_in, const int* in_sizes, int n_in,
                              void* d_out, int out_size) {
    const float* X    = (const float*)d_in[0];
    const float* A    = (const float*)d_in[1];
    const float* Wx   = (const float*)d_in[2];
    const float* Wh   = (const float*)d_in[3];
    const float* Wc   = (const float*)d_in[4];
    const float* W_ih = (const float*)d_in[5];
    const float* W_hh = (const float*)d_in[6];
    const float* b_ih = (const float*)d_in[7];
    const float* b_hh = (const float*)d_in[8];
    const float* W_fc = (const float*)d_in[9];
    const float* b_fc = (const float*)d_in[10];

    float *dXr, *dC1;
    cudaGetSymbolAddress((void**)&dXr, g_Xr);
    cudaGetSymbolAddress((void**)&dC1, g_C1);

    cudaFuncSetAttribute(step_mma, cudaFuncAttributeMaxDynamicSharedMemorySize, 2 * STG_SZ);

    setup_kernel<<<1, 128>>>(Wx, Wh, Wc, W_ih, W_hh, b_ih, b_hh);
    zero_hc_kernel<<<(NN * 64 + 255) / 256, 256>>>();
    xr_kernel<<<(NN * 1024) / 256, 256>>>(X);
    aconv_kernel<<<(NN * 512) / 256, 256>>>(A);

    // one-time precompute: C1 = A @ Xr  (fp32, exact)
    gemm_tile<<<dim3(NN / BM, 1024 / BN, 1), 256>>>(A, dXr, dC1,
                                                    NN, 1024, 1024, 0L, NN);

    for (int t = 0; t < TROLL; t++) {
        hcconv_kernel<<<(64 * 512) / 256, 256>>>();
        step_mma<<<dim3(32, MSPLIT), 256, 2 * STG_SZ>>>();
        gates_kernel<<<NN / GROWS, 128>>>(t);
    }

    final_kernel<<<NN / 256, 256>>>(W_fc, b_fc, (float*)d_out);
}

// round 10
// speedup vs baseline: 2.0067x; 1.0344x over previous
#include <cuda_runtime.h>
#include <cuda_bf16.h>
#include <math.h>
#include <cstdint>

// Problem constants
#define NN    4096
#define HDIM  32
#define TROLL 200
#define FIN   5

#define MSPLIT 4               // K-split; each CTA handles K=1024 (8 tiles of 128)
#define NKT    8               // k-tiles per CTA

// fp32 GEMM (C1 precompute) config
#define BM 256
#define BN 64
#define BK 16

typedef unsigned long long u64;

// ---------------- fp32x2 helpers (C1 precompute GEMM) -----------------------
__device__ __forceinline__ u64 pack2(float x, float y) {
    u64 r; asm("mov.b64 %0, {%1, %2};" : "=l"(r) : "f"(x), "f"(y)); return r;
}
__device__ __forceinline__ void unpack2(u64 v, float& x, float& y) {
    asm("mov.b64 {%0, %1}, %2;" : "=f"(x), "=f"(y) : "l"(v));
}
__device__ __forceinline__ void ffma2(u64& d, u64 a, u64 b) {
    asm("fma.rn.f32x2 %0, %1, %2, %0;" : "+l"(d) : "l"(a), "l"(b));
}

// ---------------- mma.sync helpers (sm_80-class, compiles for compute_103) ---
__device__ __forceinline__ uint32_t smem_u32(const void* p) {
    uint32_t a;
    asm("{ .reg .u64 t; cvta.to.shared.u64 t, %1; cvt.u32.u64 %0, t; }" : "=r"(a) : "l"(p));
    return a;
}
__device__ __forceinline__ void ldm_x4(uint32_t* r, uint32_t addr) {
    asm volatile("ldmatrix.sync.aligned.m8n8.x4.shared.b16 {%0,%1,%2,%3}, [%4];"
        : "=r"(r[0]), "=r"(r[1]), "=r"(r[2]), "=r"(r[3]) : "r"(addr));
}
__device__ __forceinline__ void mma_bf16(float* d, const uint32_t* a, uint32_t b0, uint32_t b1) {
    asm volatile("mma.sync.aligned.m16n8k16.row.col.f32.bf16.bf16.f32 "
        "{%0,%1,%2,%3}, {%4,%5,%6,%7}, {%8,%9}, {%0,%1,%2,%3};"
        : "+f"(d[0]), "+f"(d[1]), "+f"(d[2]), "+f"(d[3])
        : "r"(a[0]), "r"(a[1]), "r"(a[2]), "r"(a[3]), "r"(b0), "r"(b1));
}
__device__ __forceinline__ void cp_async16(uint32_t saddr, const void* gaddr) {
    asm volatile("cp.async.cg.shared.global [%0], [%1], 16;"
        :: "r"(saddr), "l"(gaddr) : "memory");
}
#define CP_COMMIT() asm volatile("cp.async.commit_group;" ::: "memory")

// ---------------- device scratch ---------------------------------------------
__device__ __align__(16) float g_HC[NN * 64];                      // [n][0:32]=h,[32:64]=c
__device__ __align__(16) float g_Mpart[(size_t)MSPLIT * NN * 64];  // K-split partials
__device__ __align__(16) float g_Xr[(size_t)NN * 1024];
__device__ __align__(16) float g_C1[(size_t)NN * 1024];
__device__ __align__(16) float g_U[101 * 128];
__device__ __align__(16) float g_bias[128];
// A split into bf16 hi/lo, ldmatrix-ready 128x128 tiles.
// tile (mt, ktg) at byte offset ((mt*32+ktg) << 15); inside tile:
//   byte(row, k) = row*256 + (((k>>3) ^ (row&7)) << 4) + (k&7)*2
__device__ __align__(16) __nv_bfloat16 g_Ah[(size_t)NN * NN];
__device__ __align__(16) __nv_bfloat16 g_Al[(size_t)NN * NN];
// HC^T (Bt[n][k]) split hi/lo, 64x128 tiles (16KB), tile ktg at (ktg<<14)
__device__ __align__(16) __nv_bfloat16 g_Bh[(size_t)64 * NN];
__device__ __align__(16) __nv_bfloat16 g_Bl[(size_t)64 * NN];

// ---------------- setup: fused gate matrix U ---------------------------------
__global__ void setup_kernel(const float* __restrict__ Wx, const float* __restrict__ Wh,
                             const float* __restrict__ Wc, const float* __restrict__ W_ih,
                             const float* __restrict__ W_hh, const float* __restrict__ b_ih,
                             const float* __restrict__ b_hh) {
    const int j = threadIdx.x;
    __shared__ float sWih[128 * 32];
    for (int i = j; i < 128 * 32; i += 128) sWih[i] = W_ih[i];
    __syncthreads();
    for (int r = 0; r < 32; r++) {
        float s = 0.f;
        for (int m = 0; m < 32; m++) s += Wh[r * 32 + m] * sWih[j * 32 + m];
        g_U[r * 128 + j] = s;
    }
    for (int r = 0; r < 32; r++) {
        float s = 0.f;
        for (int m = 0; m < 32; m++) s += Wc[r * 32 + m] * sWih[j * 32 + m];
        g_U[(32 + r) * 128 + j] = s;
    }
    for (int m = 0; m < 32; m++) g_U[(64 + m) * 128 + j] = W_hh[j * 32 + m];
    for (int f = 0; f < FIN; f++) {
        float s = 0.f;
        for (int m = 0; m < 32; m++) s += Wx[f * 32 + m] * sWih[j * 32 + m];
        g_U[(96 + f) * 128 + j] = s;
    }
    g_bias[j] = b_ih[j] + b_hh[j];
}

// Zero h/c state AND the bf16 B tiles (required for graph-replay determinism:
// gates now regenerates B tiles at the END of each step, so step 0 must see zeros).
__global__ void zero_state_kernel() {
    int i = blockIdx.x * blockDim.x + threadIdx.x;   // 262144 threads
    g_HC[i] = 0.f;
    g_Bh[i] = __float2bfloat16(0.f);
    g_Bl[i] = __float2bfloat16(0.f);
}

__global__ void xr_kernel(const float* __restrict__ X) {
    int idx = blockIdx.x * blockDim.x + threadIdx.x;
    int k = idx >> 10;
    int q = idx & 1023;
    float v = 0.f;
    if (q < TROLL * FIN) {
        int t = q / FIN;
        int f = q - t * FIN;
        v = X[(size_t)t * (NN * FIN) + k * FIN + f];
    }
    g_Xr[idx] = v;
}

// ---------------- A -> bf16 hi/lo ldmatrix-tiled layout (once) ----------------
__global__ void aconv_kernel(const float* __restrict__ A) {
    int idx = blockIdx.x * blockDim.x + threadIdx.x;   // NN*512 threads, 8 elems each
    int r = idx >> 9;
    int k = (idx & 511) << 3;                          // 16B chunk of 8 bf16
    int mt = r >> 7, rin = r & 127;
    int ktg = k >> 7, kin = k & 127;
    uint32_t byte = (uint32_t)(rin * 256 + ((((kin >> 3)) ^ (rin & 7)) << 4));
    size_t tile = ((size_t)(mt * 32 + ktg)) << 15;     // 32KB tiles
    unsigned short h[8], l[8];
    #pragma unroll
    for (int i = 0; i < 8; i++) {
        float x = A[(size_t)r * NN + k + i];
        __nv_bfloat16 bh = __float2bfloat16(x);
        __nv_bfloat16 bl = __float2bfloat16(x - __bfloat162float(bh));
        h[i] = __bfloat16_as_ushort(bh);
        l[i] = __bfloat16_as_ushort(bl);
    }
    uint4 vh = make_uint4((uint32_t)h[0] | ((uint32_t)h[1] << 16),
                          (uint32_t)h[2] | ((uint32_t)h[3] << 16),
                          (uint32_t)h[4] | ((uint32_t)h[5] << 16),
                          (uint32_t)h[6] | ((uint32_t)h[7] << 16));
    uint4 vl = make_uint4((uint32_t)l[0] | ((uint32_t)l[1] << 16),
                          (uint32_t)l[2] | ((uint32_t)l[3] << 16),
                          (uint32_t)l[4] | ((uint32_t)l[5] << 16),
                          (uint32_t)l[6] | ((uint32_t)l[7] << 16));
    *reinterpret_cast<uint4*>(reinterpret_cast<char*>(g_Ah) + tile + byte) = vh;
    *reinterpret_cast<uint4*>(reinterpret_cast<char*>(g_Al) + tile + byte) = vl;
}

// ---------------- step GEMM via mma.sync (HMMA path) --------------------------
// Mpart[z] = A[mt-block, z-kchunk] @ HC[z-kchunk, :]
// grid (32, MSPLIT), 256 threads = 8 warps (4m x 2n), warp tile 32x32.
// Split-precision: acc += Ah*Bh + Ah*Bl + Al*Bh.
// SMEM buffer layout (per stage): Ah 32K | Al 32K | Bh 16K | Bl 16K = 96KB
#define STG_SZ 98304
#define SM_AL  32768
#define SM_BH  65536
#define SM_BL  81920

__global__ void __launch_bounds__(256, 1) step_mma() {
    extern __shared__ __align__(16) char smem[];       // 2 * STG_SZ
    const int tid  = threadIdx.x;
    const int lane = tid & 31;
    const int wid  = tid >> 5;
    const int wm   = wid & 3;          // m-block (32 rows)
    const int wn   = wid >> 2;         // n-block (32 cols)
    const int mt   = blockIdx.x;
    const int z    = blockIdx.y;

    const uint32_t sbase = smem_u32(smem);

    auto load_tile = [&](int kt, int b) {
        const int ktg = z * NKT + kt;
        const char* gAh = reinterpret_cast<const char*>(g_Ah) + (((size_t)(mt * 32 + ktg)) << 15);
        const char* gAl = reinterpret_cast<const char*>(g_Al) + (((size_t)(mt * 32 + ktg)) << 15);
        const char* gBh = reinterpret_cast<const char*>(g_Bh) + ((size_t)ktg << 14);
        const char* gBl = reinterpret_cast<const char*>(g_Bl) + ((size_t)ktg << 14);
        const uint32_t s = sbase + b * STG_SZ;
        #pragma unroll
        for (int i = 0; i < 8; i++)
            cp_async16(s + (tid + i * 256) * 16, gAh + (tid + i * 256) * 16);
        #pragma unroll
        for (int i = 0; i < 8; i++)
            cp_async16(s + SM_AL + (tid + i * 256) * 16, gAl + (tid + i * 256) * 16);
        #pragma unroll
        for (int i = 0; i < 4; i++)
            cp_async16(s + SM_BH + (tid + i * 256) * 16, gBh + (tid + i * 256) * 16);
        #pragma unroll
        for (int i = 0; i < 4; i++)
            cp_async16(s + SM_BL + (tid + i * 256) * 16, gBl + (tid + i * 256) * 16);
        CP_COMMIT();
    };

    float acc[2][4][4];
    #pragma unroll
    for (int im = 0; im < 2; im++)
        #pragma unroll
        for (int jn = 0; jn < 4; jn++)
            #pragma unroll
            for (int q = 0; q < 4; q++) acc[im][jn][q] = 0.f;

    load_tile(0, 0);
    load_tile(1, 1);

    const int arow[2] = { wm * 32 + (lane & 15), wm * 32 + 16 + (lane & 15) };
    const int acolh   = (lane >> 4);
    const int nrow[2] = { wn * 32 + (lane & 7) + ((lane >> 4) << 3),
                          wn * 32 + 16 + (lane & 7) + ((lane >> 4) << 3) };
    const int bcolh   = (lane >> 3) & 1;

    #pragma unroll
    for (int kt = 0; kt < NKT; kt++) {
        const int b = kt & 1;
        if (kt == NKT - 1) asm volatile("cp.async.wait_group 0;" ::: "memory");
        else               asm volatile("cp.async.wait_group 1;" ::: "memory");
        __syncthreads();

        const uint32_t sA   = sbase + b * STG_SZ;
        const uint32_t sAl_ = sA + SM_AL;
        const uint32_t sBh_ = sA + SM_BH;
        const uint32_t sBl_ = sA + SM_BL;

        #pragma unroll
        for (int ks = 0; ks < 8; ks++) {
            const int ck = ks * 2;
            uint32_t ah[2][4], al[2][4], bh[2][4], bl[2][4];
            #pragma unroll
            for (int im = 0; im < 2; im++) {
                const int r = arow[im];
                const uint32_t off = (uint32_t)(r * 256 + (((ck + acolh) ^ (r & 7)) << 4));
                ldm_x4(ah[im], sA   + off);
                ldm_x4(al[im], sAl_ + off);
            }
            #pragma unroll
            for (int g = 0; g < 2; g++) {
                const int r = nrow[g];
                const uint32_t off = (uint32_t)(r * 256 + (((ck + bcolh) ^ (r & 7)) << 4));
                ldm_x4(bh[g], sBh_ + off);
                ldm_x4(bl[g], sBl_ + off);
            }
            #pragma unroll
            for (int im = 0; im < 2; im++)
                #pragma unroll
                for (int jn = 0; jn < 4; jn++) {
                    const int g = jn >> 1, w = (jn & 1) * 2;
                    mma_bf16(acc[im][jn], ah[im], bh[g][w], bh[g][w + 1]);
                    mma_bf16(acc[im][jn], ah[im], bl[g][w], bl[g][w + 1]);
                    mma_bf16(acc[im][jn], al[im], bh[g][w], bh[g][w + 1]);
                }
        }
        __syncthreads();
        if (kt + 2 < NKT) load_tile(kt + 2, b);
    }

    float* base = g_Mpart + (size_t)z * NN * 64;
    const int row0 = mt * 128 + wm * 32 + (lane >> 2);
    const int col0 = wn * 32 + (lane & 3) * 2;
    #pragma unroll
    for (int im = 0; im < 2; im++)
        #pragma unroll
        for (int jn = 0; jn < 4; jn++) {
            const int r = row0 + im * 16;
            const int c = col0 + jn * 8;
            *reinterpret_cast<float2*>(&base[(size_t)r * 64 + c]) =
                make_float2(acc[im][jn][0], acc[im][jn][1]);
            *reinterpret_cast<float2*>(&base[(size_t)(r + 8) * 64 + c]) =
                make_float2(acc[im][jn][2], acc[im][jn][3]);
        }
}

// ---------------- fp32 GEMM with FFMA2 (C1 precompute only) -------------------
__global__ void __launch_bounds__(256, 1) gemm_tile(
    const float* __restrict__ A, const float* __restrict__ B,
    float* __restrict__ C, int lda, int ldb, int ldc,
    long zstride, int kchunk)
{
    __shared__ __align__(16) float As[2][BK][BM];
    __shared__ __align__(16) float Bs[2][BK][BN];
    const int tid = threadIdx.x;
    const int tr = tid >> 3, tc = tid & 7;
    const int row0 = blockIdx.x * BM, col0 = blockIdx.y * BN;
    const int k0 = blockIdx.z * kchunk;
    const int lr = tid >> 2, lc = (tid & 3) * 4;
    const int brow = tid >> 4, bcol = (tid & 15) * 4;
    const float* Abase = A + (size_t)(row0 + lr) * lda + lc;
    const float* Bbase = B + (size_t)brow * ldb + col0 + bcol;

    u64 acc[4][8];
    #pragma unroll
    for (int i = 0; i < 4; i++)
        #pragma unroll
        for (int j = 0; j < 8; j++) acc[i][j] = 0ull;

    const int ntiles = kchunk / BK;
    float4 av[4]; float4 bv;
    {
        const float* Ap = Abase + k0;
        #pragma unroll
        for (int p = 0; p < 4; p++)
            av[p] = *reinterpret_cast<const float4*>(Ap + (size_t)(p * 64) * lda);
        bv = *reinterpret_cast<const float4*>(Bbase + (size_t)k0 * ldb);
    }
    #pragma unroll
    for (int p = 0; p < 4; p++) {
        As[0][lc + 0][p * 64 + lr] = av[p].x;
        As[0][lc + 1][p * 64 + lr] = av[p].y;
        As[0][lc + 2][p * 64 + lr] = av[p].z;
        As[0][lc + 3][p * 64 + lr] = av[p].w;
    }
    *reinterpret_cast<float4*>(&Bs[0][brow][bcol]) = bv;
    __syncthreads();

    int buf = 0;
    for (int kt = 0; kt < ntiles; kt++) {
        const bool has_next = (kt + 1 < ntiles);
        if (has_next) {
            const int kk = k0 + (kt + 1) * BK;
            const float* Ap = Abase + kk;
            #pragma unroll
            for (int p = 0; p < 4; p++)
                av[p] = *reinterpret_cast<const float4*>(Ap + (size_t)(p * 64) * lda);
            bv = *reinterpret_cast<const float4*>(Bbase + (size_t)kk * ldb);
        }
        #pragma unroll
        for (int k = 0; k < BK; k++) {
            ulonglong2 A0 = *reinterpret_cast<const ulonglong2*>(&As[buf][k][tr * 8]);
            ulonglong2 A1 = *reinterpret_cast<const ulonglong2*>(&As[buf][k][tr * 8 + 4]);
            float4 b0 = *reinterpret_cast<const float4*>(&Bs[buf][k][tc * 8]);
            float4 b1 = *reinterpret_cast<const float4*>(&Bs[buf][k][tc * 8 + 4]);
            u64 ar[4] = {A0.x, A0.y, A1.x, A1.y};
            u64 bb[8] = {pack2(b0.x, b0.x), pack2(b0.y, b0.y), pack2(b0.z, b0.z), pack2(b0.w, b0.w),
                         pack2(b1.x, b1.x), pack2(b1.y, b1.y), pack2(b1.z, b1.z), pack2(b1.w, b1.w)};
            #pragma unroll
            for (int ii = 0; ii < 4; ii++)
                #pragma unroll
                for (int j = 0; j < 8; j++)
                    ffma2(acc[ii][j], ar[ii], bb[j]);
        }
        if (has_next) {
            const int nb = buf ^ 1;
            #pragma unroll
            for (int p = 0; p < 4; p++) {
                As[nb][lc + 0][p * 64 + lr] = av[p].x;
                As[nb][lc + 1][p * 64 + lr] = av[p].y;
                As[nb][lc + 2][p * 64 + lr] = av[p].z;
                As[nb][lc + 3][p * 64 + lr] = av[p].w;
            }
            *reinterpret_cast<float4*>(&Bs[nb][brow][bcol]) = bv;
        }
        __syncthreads();
        buf ^= 1;
    }

    float* Cp = C + (size_t)blockIdx.z * zstride + (size_t)(row0 + tr * 8) * ldc + col0 + tc * 8;
    #pragma unroll
    for (int ii = 0; ii < 4; ii++) {
        float lo[8], hi[8];
        #pragma unroll
        for (int j = 0; j < 8; j++) unpack2(acc[ii][j], lo[j], hi[j]);
        float* r0 = Cp + (size_t)(2 * ii) * ldc;
        float* r1 = Cp + (size_t)(2 * ii + 1) * ldc;
        *reinterpret_cast<float4*>(r0)     = make_float4(lo[0], lo[1], lo[2], lo[3]);
        *reinterpret_cast<float4*>(r0 + 4) = make_float4(lo[4], lo[5], lo[6], lo[7]);
        *reinterpret_cast<float4*>(r1)     = make_float4(hi[0], hi[1], hi[2], hi[3]);
        *reinterpret_cast<float4*>(r1 + 4) = make_float4(hi[4], hi[5], hi[6], hi[7]);
    }
}

// ---------------- gates + LSTM update + B-tile regeneration -------------------
// Reduces K-split partials, applies fused gate matrix U, LSTM nonlinearity,
// writes new h,c to g_HC AND writes the bf16 hi/lo ldmatrix tiles (g_Bh/g_Bl)
// directly — this replaces the former per-step hcconv kernel.
#define GROWS 16
__global__ void __launch_bounds__(128) gates_kernel(int t) {
    const int tid = threadIdx.x;
    __shared__ float sv[101];
    __shared__ float sg[128];

    float uj[101];
    #pragma unroll
    for (int k = 0; k < 101; k++) uj[k] = g_U[k * 128 + tid];
    const float bj = g_bias[tid];

    const int row_base = blockIdx.x * GROWS;
    for (int r = 0; r < GROWS; r++) {
        const int n = row_base + r;
        if (tid < 64) {
            float s = 0.f;
            #pragma unroll
            for (int zz = 0; zz < MSPLIT; zz++)
                s += g_Mpart[((size_t)zz * NN + n) * 64 + tid];
            sv[tid] = s;
        } else if (tid < 96) {
            sv[tid] = g_HC[n * 64 + (tid - 64)];
        } else if (tid < 101) {
            sv[tid] = g_C1[(size_t)n * 1024 + t * FIN + (tid - 96)];
        }
        __syncthreads();

        float g = bj;
        #pragma unroll
        for (int k = 0; k < 101; k++) g += sv[k] * uj[k];
        sg[tid] = g;
        __syncthreads();

        if (tid < 32) {
            float ii = 1.f / (1.f + expf(-sg[tid]));
            float ff = 1.f / (1.f + expf(-sg[32 + tid]));
            float gg = tanhf(sg[64 + tid]);
            float oo = 1.f / (1.f + expf(-sg[96 + tid]));
            float c_old = g_HC[n * 64 + 32 + tid];
            float c_new = ff * c_old + ii * gg;
            float h_new = oo * tanhf(c_new);
            g_HC[n * 64 + tid] = h_new;
            g_HC[n * 64 + 32 + tid] = c_new;

            // --- write bf16 hi/lo B-tiles (layout: tile ktg=n>>7 at ktg<<14;
            //     byte(bRow,kin) = bRow*256 + (((kin>>3)^(bRow&7))<<4) + (kin&7)*2 )
            const int ktg = n >> 7, kin = n & 127;
            const size_t tbase = (size_t)ktg << 14;
            const uint32_t kpart = (uint32_t)(((kin >> 3) & 0xF) << 4);
            const uint32_t klow  = (uint32_t)((kin & 7) * 2);
            char* const pBh = reinterpret_cast<char*>(g_Bh) + tbase;
            char* const pBl = reinterpret_cast<char*>(g_Bl) + tbase;

            __nv_bfloat16 hh = __float2bfloat16(h_new);
            __nv_bfloat16 hl = __float2bfloat16(h_new - __bfloat162float(hh));
            __nv_bfloat16 ch = __float2bfloat16(c_new);
            __nv_bfloat16 cl = __float2bfloat16(c_new - __bfloat162float(ch));

            const uint32_t bh_row = (uint32_t)tid;          // h -> bRow 0..31
            const uint32_t bc_row = (uint32_t)(tid + 32);   // c -> bRow 32..63
            const uint32_t offh = bh_row * 256 + ((kpart ^ ((bh_row & 7) << 4))) + klow;
            const uint32_t offc = bc_row * 256 + ((kpart ^ ((bc_row & 7) << 4))) + klow;
            *reinterpret_cast<__nv_bfloat16*>(pBh + offh) = hh;
            *reinterpret_cast<__nv_bfloat16*>(pBl + offh) = hl;
            *reinterpret_cast<__nv_bfloat16*>(pBh + offc) = ch;
            *reinterpret_cast<__nv_bfloat16*>(pBl + offc) = cl;
        }
        __syncthreads();
    }
}

// ---------------- final projection --------------------------------------------
__global__ void final_kernel(const float* __restrict__ W_fc,
                             const float* __restrict__ b_fc,
                             float* __restrict__ out) {
    int n = blockIdx.x * blockDim.x + threadIdx.x;
    if (n >= NN) return;
    float s = b_fc[0];
    #pragma unroll
    for (int u = 0; u < HDIM; u++) s += g_HC[n * 64 + u] * W_fc[u];
    out[n] = s;
}

// ---------------- launch --------------------------------------------------------
extern "C" void kernel_launch(void* const* d_in, const int* in_sizes, int n_in,
                              void* d_out, int out_size) {
    const float* X    = (const float*)d_in[0];
    const float* A    = (const float*)d_in[1];
    const float* Wx   = (const float*)d_in[2];
    const float* Wh   = (const float*)d_in[3];
    const float* Wc   = (const float*)d_in[4];
    const float* W_ih = (const float*)d_in[5];
    const float* W_hh = (const float*)d_in[6];
    const float* b_ih = (const float*)d_in[7];
    const float* b_hh = (const float*)d_in[8];
    const float* W_fc = (const float*)d_in[9];
    const float* b_fc = (const float*)d_in[10];

    float *dXr, *dC1;
    cudaGetSymbolAddress((void**)&dXr, g_Xr);
    cudaGetSymbolAddress((void**)&dC1, g_C1);

    cudaFuncSetAttribute(step_mma, cudaFuncAttributeMaxDynamicSharedMemorySize, 2 * STG_SZ);

    setup_kernel<<<1, 128>>>(Wx, Wh, Wc, W_ih, W_hh, b_ih, b_hh);
    zero_state_kernel<<<(NN * 64) / 256, 256>>>();
    xr_kernel<<<(NN * 1024) / 256, 256>>>(X);
    aconv_kernel<<<(NN * 512) / 256, 256>>>(A);

    // one-time precompute: C1 = A @ Xr  (fp32, exact)
    gemm_tile<<<dim3(NN / BM, 1024 / BN, 1), 256>>>(A, dXr, dC1,
                                                    NN, 1024, 1024, 0L, NN);

    for (int t = 0; t < TROLL; t++) {
        step_mma<<<dim3(32, MSPLIT), 256, 2 * STG_SZ>>>();
        gates_kernel<<<NN / GROWS, 128>>>(t);   // also regenerates B tiles
    }

    final_kernel<<<NN / 256, 256>>>(W_fc, b_fc, (float*)d_out);
}

// round 11
// speedup vs baseline: 2.8231x; 1.4068x over previous
#include <cuda_runtime.h>
#include <cuda_bf16.h>
#include <math.h>
#include <cstdint>

// Problem constants
#define NN    4096
#define HDIM  32
#define TROLL 200
#define FIN   5

#define MSPLIT 4               // K-split for step GEMM; each CTA does K=1024
#define NKT    8               // k-tiles per step CTA
#define NCTA   128             // persistent grid size (mt*4 + z)

typedef unsigned long long u64;

// ---------------- fp32x2 / mma helpers ---------------------------------------
__device__ __forceinline__ u64 pack2(float x, float y) {
    u64 r; asm("mov.b64 %0, {%1, %2};" : "=l"(r) : "f"(x), "f"(y)); return r;
}
__device__ __forceinline__ void unpack2(u64 v, float& x, float& y) {
    asm("mov.b64 {%0, %1}, %2;" : "=f"(x), "=f"(y) : "l"(v));
}
__device__ __forceinline__ void ffma2(u64& d, u64 a, u64 b) {
    asm("fma.rn.f32x2 %0, %1, %2, %0;" : "+l"(d) : "l"(a), "l"(b));
}
__device__ __forceinline__ uint32_t smem_u32(const void* p) {
    uint32_t a;
    asm("{ .reg .u64 t; cvta.to.shared.u64 t, %1; cvt.u32.u64 %0, t; }" : "=r"(a) : "l"(p));
    return a;
}
__device__ __forceinline__ void ldm_x4(uint32_t* r, uint32_t addr) {
    asm volatile("ldmatrix.sync.aligned.m8n8.x4.shared.b16 {%0,%1,%2,%3}, [%4];"
        : "=r"(r[0]), "=r"(r[1]), "=r"(r[2]), "=r"(r[3]) : "r"(addr));
}
__device__ __forceinline__ void mma_bf16(float* d, const uint32_t* a, uint32_t b0, uint32_t b1) {
    asm volatile("mma.sync.aligned.m16n8k16.row.col.f32.bf16.bf16.f32 "
        "{%0,%1,%2,%3}, {%4,%5,%6,%7}, {%8,%9}, {%0,%1,%2,%3};"
        : "+f"(d[0]), "+f"(d[1]), "+f"(d[2]), "+f"(d[3])
        : "r"(a[0]), "r"(a[1]), "r"(a[2]), "r"(a[3]), "r"(b0), "r"(b1));
}
__device__ __forceinline__ void cp_async16(uint32_t saddr, const void* gaddr) {
    asm volatile("cp.async.cg.shared.global [%0], [%1], 16;"
        :: "r"(saddr), "l"(gaddr) : "memory");
}
#define CP_COMMIT() asm volatile("cp.async.commit_group;" ::: "memory")

// ---------------- device scratch ---------------------------------------------
__device__ __align__(16) float g_HC[NN * 64];                      // [n][0:32]=h,[32:64]=c
__device__ __align__(16) float g_Mpart[(size_t)MSPLIT * NN * 64];  // K-split partials
__device__ __align__(16) float g_C1[(size_t)NN * 1024];            // A @ Xr (fp32 result)
__device__ __align__(16) float g_U[101 * 128];
__device__ __align__(16) float g_bias[128];
__device__ __align__(16) float g_U4[13056];                        // repacked: [(k*32+l)*4+q] = U[k][l+32q]; last 128 = bias4
__device__ unsigned g_ctr;                                          // grid barrier counter
// A split into bf16 hi/lo, ldmatrix-ready 128x128 tiles.
// tile (mt, ktg) at ((mt*32+ktg) << 15); byte(row,k)=row*256+(((k>>3)^(row&7))<<4)+(k&7)*2
__device__ __align__(16) __nv_bfloat16 g_Ah[(size_t)NN * NN];
__device__ __align__(16) __nv_bfloat16 g_Al[(size_t)NN * NN];
// HC^T (Bt[n][k]) split hi/lo, 64x128 tiles (16KB), tile ktg at (ktg<<14)
__device__ __align__(16) __nv_bfloat16 g_Bh[(size_t)64 * NN];
__device__ __align__(16) __nv_bfloat16 g_Bl[(size_t)64 * NN];
// Xr^T (Bt[q][kk]) split hi/lo, 64x128 tiles, tile (ktg,nt) at ((nt*32+ktg)<<14)
__device__ __align__(16) __nv_bfloat16 g_XBh[(size_t)1024 * NN];
__device__ __align__(16) __nv_bfloat16 g_XBl[(size_t)1024 * NN];

// ---------------- setup: fused gate matrix U + repacked U4 -------------------
__global__ void setup_kernel(const float* __restrict__ Wx, const float* __restrict__ Wh,
                             const float* __restrict__ Wc, const float* __restrict__ W_ih,
                             const float* __restrict__ W_hh, const float* __restrict__ b_ih,
                             const float* __restrict__ b_hh) {
    const int j = threadIdx.x;
    __shared__ float sWih[128 * 32];
    for (int i = j; i < 128 * 32; i += 128) sWih[i] = W_ih[i];
    __syncthreads();
    for (int r = 0; r < 32; r++) {
        float s = 0.f;
        for (int m = 0; m < 32; m++) s += Wh[r * 32 + m] * sWih[j * 32 + m];
        g_U[r * 128 + j] = s;
    }
    for (int r = 0; r < 32; r++) {
        float s = 0.f;
        for (int m = 0; m < 32; m++) s += Wc[r * 32 + m] * sWih[j * 32 + m];
        g_U[(32 + r) * 128 + j] = s;
    }
    for (int m = 0; m < 32; m++) g_U[(64 + m) * 128 + j] = W_hh[j * 32 + m];
    for (int f = 0; f < FIN; f++) {
        float s = 0.f;
        for (int m = 0; m < 32; m++) s += Wx[f * 32 + m] * sWih[j * 32 + m];
        g_U[(96 + f) * 128 + j] = s;
    }
    g_bias[j] = b_ih[j] + b_hh[j];
    __syncthreads();
    // repack: g_U4[(k*32+l)*4+q] = U[k][l+32q]; bias4 at index 3232
    {
        const int l = j & 31, q = j >> 5;
        for (int k = 0; k < 101; k++)
            g_U4[(k * 32 + l) * 4 + q] = g_U[k * 128 + l + 32 * q];
        g_U4[(101 * 32 + l) * 4 + q] = g_bias[l + 32 * q];
    }
}

// Zero h/c, B tiles, and grid-barrier counter (graph-replay determinism).
__global__ void zero_state_kernel() {
    int i = blockIdx.x * blockDim.x + threadIdx.x;   // 262144 threads
    g_HC[i] = 0.f;
    g_Bh[i] = __float2bfloat16(0.f);
    g_Bl[i] = __float2bfloat16(0.f);
    if (i == 0) g_ctr = 0u;
}

// ---------------- A -> bf16 hi/lo ldmatrix tiles (once) -----------------------
__global__ void aconv_kernel(const float* __restrict__ A) {
    int idx = blockIdx.x * blockDim.x + threadIdx.x;   // NN*512 threads, 8 elems each
    int r = idx >> 9;
    int k = (idx & 511) << 3;
    int mt = r >> 7, rin = r & 127;
    int ktg = k >> 7, kin = k & 127;
    uint32_t byte = (uint32_t)(rin * 256 + ((((kin >> 3)) ^ (rin & 7)) << 4));
    size_t tile = ((size_t)(mt * 32 + ktg)) << 15;
    unsigned short h[8], l[8];
    #pragma unroll
    for (int i = 0; i < 8; i++) {
        float x = A[(size_t)r * NN + k + i];
        __nv_bfloat16 bh = __float2bfloat16(x);
        __nv_bfloat16 bl = __float2bfloat16(x - __bfloat162float(bh));
        h[i] = __bfloat16_as_ushort(bh);
        l[i] = __bfloat16_as_ushort(bl);
    }
    uint4 vh = make_uint4((uint32_t)h[0] | ((uint32_t)h[1] << 16),
                          (uint32_t)h[2] | ((uint32_t)h[3] << 16),
                          (uint32_t)h[4] | ((uint32_t)h[5] << 16),
                          (uint32_t)h[6] | ((uint32_t)h[7] << 16));
    uint4 vl = make_uint4((uint32_t)l[0] | ((uint32_t)l[1] << 16),
                          (uint32_t)l[2] | ((uint32_t)l[3] << 16),
                          (uint32_t)l[4] | ((uint32_t)l[5] << 16),
                          (uint32_t)l[6] | ((uint32_t)l[7] << 16));
    *reinterpret_cast<uint4*>(reinterpret_cast<char*>(g_Ah) + tile + byte) = vh;
    *reinterpret_cast<uint4*>(reinterpret_cast<char*>(g_Al) + tile + byte) = vl;
}

// ---------------- X -> Xr^T bf16 hi/lo ldmatrix tiles (once) ------------------
// Bt[q][kk] = Xr[kk][q] = X[t][kk][f] (q = t*5+f < 1000, else 0)
__global__ void xrconv_kernel(const float* __restrict__ X) {
    int idx = blockIdx.x * blockDim.x + threadIdx.x;   // 1024*512 threads
    int q  = idx >> 9;                                 // 0..1023 (n dim)
    int kk = (idx & 511) << 3;                         // k chunk of 8
    int nt = q >> 6, rown = q & 63;
    int ktg = kk >> 7, kin = kk & 127;
    uint32_t byte = (uint32_t)(rown * 256 + ((((kin >> 3)) ^ (rown & 7)) << 4));
    size_t tile = ((size_t)(nt * 32 + ktg)) << 14;
    const bool valid = (q < TROLL * FIN);
    const int t = q / FIN, f = q - t * FIN;
    unsigned short h[8], l[8];
    #pragma unroll
    for (int i = 0; i < 8; i++) {
        float x = valid ? X[((size_t)t * NN + kk + i) * FIN + f] : 0.f;
        __nv_bfloat16 bh = __float2bfloat16(x);
        __nv_bfloat16 bl = __float2bfloat16(x - __bfloat162float(bh));
        h[i] = __bfloat16_as_ushort(bh);
        l[i] = __bfloat16_as_ushort(bl);
    }
    uint4 vh = make_uint4((uint32_t)h[0] | ((uint32_t)h[1] << 16),
                          (uint32_t)h[2] | ((uint32_t)h[3] << 16),
                          (uint32_t)h[4] | ((uint32_t)h[5] << 16),
                          (uint32_t)h[6] | ((uint32_t)h[7] << 16));
    uint4 vl = make_uint4((uint32_t)l[0] | ((uint32_t)l[1] << 16),
                          (uint32_t)l[2] | ((uint32_t)l[3] << 16),
                          (uint32_t)l[4] | ((uint32_t)l[5] << 16),
                          (uint32_t)l[6] | ((uint32_t)l[7] << 16));
    *reinterpret_cast<uint4*>(reinterpret_cast<char*>(g_XBh) + tile + byte) = vh;
    *reinterpret_cast<uint4*>(reinterpret_cast<char*>(g_XBl) + tile + byte) = vl;
}

// ---------------- shared SMEM stage layout ------------------------------------
#define STG_SZ 98304          // Ah 32K | Al 32K | Bh 16K | Bl 16K
#define SM_AL  32768
#define SM_BH  65536
#define SM_BL  81920

// ---------------- C1 = A @ Xr via mma.sync (one-time, no K-split) -------------
// grid (32 mt, 16 nt), 256 threads, 32 k-tiles per CTA, fp32 out to g_C1.
__global__ void __launch_bounds__(256, 1) c1_mma() {
    extern __shared__ __align__(16) char smem[];
    const int tid  = threadIdx.x;
    const int lane = tid & 31;
    const int wid  = tid >> 5;
    const int wm   = wid & 3;
    const int wn   = wid >> 2;
    const int mt   = blockIdx.x;
    const int nt   = blockIdx.y;
    const uint32_t sbase = smem_u32(smem);

    auto load_tile = [&](int kt, int b) {
        const char* gAh = reinterpret_cast<const char*>(g_Ah) + (((size_t)(mt * 32 + kt)) << 15);
        const char* gAl = reinterpret_cast<const char*>(g_Al) + (((size_t)(mt * 32 + kt)) << 15);
        const char* gBh = reinterpret_cast<const char*>(g_XBh) + (((size_t)(nt * 32 + kt)) << 14);
        const char* gBl = reinterpret_cast<const char*>(g_XBl) + (((size_t)(nt * 32 + kt)) << 14);
        const uint32_t s = sbase + b * STG_SZ;
        #pragma unroll
        for (int i = 0; i < 8; i++)
            cp_async16(s + (tid + i * 256) * 16, gAh + (tid + i * 256) * 16);
        #pragma unroll
        for (int i = 0; i < 8; i++)
            cp_async16(s + SM_AL + (tid + i * 256) * 16, gAl + (tid + i * 256) * 16);
        #pragma unroll
        for (int i = 0; i < 4; i++)
            cp_async16(s + SM_BH + (tid + i * 256) * 16, gBh + (tid + i * 256) * 16);
        #pragma unroll
        for (int i = 0; i < 4; i++)
            cp_async16(s + SM_BL + (tid + i * 256) * 16, gBl + (tid + i * 256) * 16);
        CP_COMMIT();
    };

    float acc[2][4][4];
    #pragma unroll
    for (int im = 0; im < 2; im++)
        #pragma unroll
        for (int jn = 0; jn < 4; jn++)
            #pragma unroll
            for (int q = 0; q < 4; q++) acc[im][jn][q] = 0.f;

    load_tile(0, 0);
    load_tile(1, 1);

    const int arow[2] = { wm * 32 + (lane & 15), wm * 32 + 16 + (lane & 15) };
    const int acolh   = (lane >> 4);
    const int nrow[2] = { wn * 32 + (lane & 7) + ((lane >> 4) << 3),
                          wn * 32 + 16 + (lane & 7) + ((lane >> 4) << 3) };
    const int bcolh   = (lane >> 3) & 1;

    for (int kt = 0; kt < 32; kt++) {
        const int b = kt & 1;
        if (kt == 31) asm volatile("cp.async.wait_group 0;" ::: "memory");
        else          asm volatile("cp.async.wait_group 1;" ::: "memory");
        __syncthreads();

        const uint32_t sA   = sbase + b * STG_SZ;
        const uint32_t sAl_ = sA + SM_AL;
        const uint32_t sBh_ = sA + SM_BH;
        const uint32_t sBl_ = sA + SM_BL;

        #pragma unroll
        for (int ks = 0; ks < 8; ks++) {
            const int ck = ks * 2;
            uint32_t ah[2][4], al[2][4], bh[2][4], bl[2][4];
            #pragma unroll
            for (int im = 0; im < 2; im++) {
                const int r = arow[im];
                const uint32_t off = (uint32_t)(r * 256 + (((ck + acolh) ^ (r & 7)) << 4));
                ldm_x4(ah[im], sA   + off);
                ldm_x4(al[im], sAl_ + off);
            }
            #pragma unroll
            for (int g = 0; g < 2; g++) {
                const int r = nrow[g];
                const uint32_t off = (uint32_t)(r * 256 + (((ck + bcolh) ^ (r & 7)) << 4));
                ldm_x4(bh[g], sBh_ + off);
                ldm_x4(bl[g], sBl_ + off);
            }
            #pragma unroll
            for (int im = 0; im < 2; im++)
                #pragma unroll
                for (int jn = 0; jn < 4; jn++) {
                    const int g = jn >> 1, w = (jn & 1) * 2;
                    mma_bf16(acc[im][jn], ah[im], bh[g][w], bh[g][w + 1]);
                    mma_bf16(acc[im][jn], ah[im], bl[g][w], bl[g][w + 1]);
                    mma_bf16(acc[im][jn], al[im], bh[g][w], bh[g][w + 1]);
                }
        }
        __syncthreads();
        if (kt + 2 < 32) load_tile(kt + 2, b);
    }

    const int row0 = mt * 128 + wm * 32 + (lane >> 2);
    const int col0 = nt * 64 + wn * 32 + (lane & 3) * 2;
    #pragma unroll
    for (int im = 0; im < 2; im++)
        #pragma unroll
        for (int jn = 0; jn < 4; jn++) {
            const int r = row0 + im * 16;
            const int c = col0 + jn * 8;
            *reinterpret_cast<float2*>(&g_C1[(size_t)r * 1024 + c]) =
                make_float2(acc[im][jn][0], acc[im][jn][1]);
            *reinterpret_cast<float2*>(&g_C1[(size_t)(r + 8) * 1024 + c]) =
                make_float2(acc[im][jn][2], acc[im][jn][3]);
        }
}

// ---------------- grid barrier (persistent kernel) -----------------------------
__device__ __forceinline__ void grid_sync(unsigned goal) {
    __syncthreads();
    if (threadIdx.x == 0) {
        __threadfence();
        atomicAdd(&g_ctr, 1u);
        unsigned v;
        do {
            asm volatile("ld.acquire.gpu.global.u32 %0, [%1];" : "=r"(v) : "l"(&g_ctr) : "memory");
        } while (v < goal);
    }
    __syncthreads();
}

// ---------------- persistent fused step loop -----------------------------------
// 128 CTAs x 256 threads, 1 CTA/SM. Per step:
//   phase A: mma for (mt = bid>>2, z = bid&3)  -> Mpart
//   grid barrier
//   phase B: gates for nodes [bid*32, bid*32+32) -> HC + B tiles
//   grid barrier
// Final: out projection for own nodes.
__global__ void __launch_bounds__(256, 1) fused_steps(const float* __restrict__ W_fc,
                                                      const float* __restrict__ b_fc,
                                                      float* __restrict__ out) {
    extern __shared__ __align__(16) char smem[];
    const int tid  = threadIdx.x;
    const int lane = tid & 31;
    const int wid  = tid >> 5;
    const int wm   = wid & 3;
    const int wn   = wid >> 2;
    const int bid  = blockIdx.x;
    const int mt   = bid >> 2;
    const int z    = bid & 3;
    const uint32_t sbase = smem_u32(smem);

    auto load_tile = [&](int kt, int b) {
        const int ktg = z * NKT + kt;
        const char* gAh = reinterpret_cast<const char*>(g_Ah) + (((size_t)(mt * 32 + ktg)) << 15);
        const char* gAl = reinterpret_cast<const char*>(g_Al) + (((size_t)(mt * 32 + ktg)) << 15);
        const char* gBh = reinterpret_cast<const char*>(g_Bh) + ((size_t)ktg << 14);
        const char* gBl = reinterpret_cast<const char*>(g_Bl) + ((size_t)ktg << 14);
        const uint32_t s = sbase + b * STG_SZ;
        #pragma unroll
        for (int i = 0; i < 8; i++)
            cp_async16(s + (tid + i * 256) * 16, gAh + (tid + i * 256) * 16);
        #pragma unroll
        for (int i = 0; i < 8; i++)
            cp_async16(s + SM_AL + (tid + i * 256) * 16, gAl + (tid + i * 256) * 16);
        #pragma unroll
        for (int i = 0; i < 4; i++)
            cp_async16(s + SM_BH + (tid + i * 256) * 16, gBh + (tid + i * 256) * 16);
        #pragma unroll
        for (int i = 0; i < 4; i++)
            cp_async16(s + SM_BL + (tid + i * 256) * 16, gBl + (tid + i * 256) * 16);
        CP_COMMIT();
    };

    const int arow[2] = { wm * 32 + (lane & 15), wm * 32 + 16 + (lane & 15) };
    const int acolh   = (lane >> 4);
    const int nrow[2] = { wn * 32 + (lane & 7) + ((lane >> 4) << 3),
                          wn * 32 + 16 + (lane & 7) + ((lane >> 4) << 3) };
    const int bcolh   = (lane >> 3) & 1;

    unsigned bar = 0;

    for (int t = 0; t < TROLL; t++) {
        // ================= phase A: step GEMM =================
        float acc[2][4][4];
        #pragma unroll
        for (int im = 0; im < 2; im++)
            #pragma unroll
            for (int jn = 0; jn < 4; jn++)
                #pragma unroll
                for (int q = 0; q < 4; q++) acc[im][jn][q] = 0.f;

        load_tile(0, 0);
        load_tile(1, 1);

        #pragma unroll
        for (int kt = 0; kt < NKT; kt++) {
            const int b = kt & 1;
            if (kt == NKT - 1) asm volatile("cp.async.wait_group 0;" ::: "memory");
            else               asm volatile("cp.async.wait_group 1;" ::: "memory");
            __syncthreads();

            const uint32_t sA   = sbase + b * STG_SZ;
            const uint32_t sAl_ = sA + SM_AL;
            const uint32_t sBh_ = sA + SM_BH;
            const uint32_t sBl_ = sA + SM_BL;

            #pragma unroll
            for (int ks = 0; ks < 8; ks++) {
                const int ck = ks * 2;
                uint32_t ah[2][4], al[2][4], bh[2][4], bl[2][4];
                #pragma unroll
                for (int im = 0; im < 2; im++) {
                    const int r = arow[im];
                    const uint32_t off = (uint32_t)(r * 256 + (((ck + acolh) ^ (r & 7)) << 4));
                    ldm_x4(ah[im], sA   + off);
                    ldm_x4(al[im], sAl_ + off);
                }
                #pragma unroll
                for (int g = 0; g < 2; g++) {
                    const int r = nrow[g];
                    const uint32_t off = (uint32_t)(r * 256 + (((ck + bcolh) ^ (r & 7)) << 4));
                    ldm_x4(bh[g], sBh_ + off);
                    ldm_x4(bl[g], sBl_ + off);
                }
                #pragma unroll
                for (int im = 0; im < 2; im++)
                    #pragma unroll
                    for (int jn = 0; jn < 4; jn++) {
                        const int g = jn >> 1, w = (jn & 1) * 2;
                        mma_bf16(acc[im][jn], ah[im], bh[g][w], bh[g][w + 1]);
                        mma_bf16(acc[im][jn], ah[im], bl[g][w], bl[g][w + 1]);
                        mma_bf16(acc[im][jn], al[im], bh[g][w], bh[g][w + 1]);
                    }
            }
            __syncthreads();
            if (kt + 2 < NKT) load_tile(kt + 2, b);
        }

        {
            float* base = g_Mpart + (size_t)z * NN * 64;
            const int row0 = mt * 128 + wm * 32 + (lane >> 2);
            const int col0 = wn * 32 + (lane & 3) * 2;
            #pragma unroll
            for (int im = 0; im < 2; im++)
                #pragma unroll
                for (int jn = 0; jn < 4; jn++) {
                    const int r = row0 + im * 16;
                    const int c = col0 + jn * 8;
                    *reinterpret_cast<float2*>(&base[(size_t)r * 64 + c]) =
                        make_float2(acc[im][jn][0], acc[im][jn][1]);
                    *reinterpret_cast<float2*>(&base[(size_t)(r + 8) * 64 + c]) =
                        make_float2(acc[im][jn][2], acc[im][jn][3]);
                }
        }

        grid_sync(++bar * NCTA);

        // ================= phase B: gates (overlay smem) =================
        {
            float4* Us4 = reinterpret_cast<float4*>(smem);        // 3232 f4 U + 32 f4 bias
            const float4* gU4 = reinterpret_cast<const float4*>(g_U4);
            for (int i = tid; i < 3264; i += 256) Us4[i] = gU4[i];
            float* svall = reinterpret_cast<float*>(Us4 + 3264);  // 8 warps * 104 floats
            __syncthreads();

            float* sv = svall + wid * 104;
            const float4 bb = Us4[3232 + lane];

            #pragma unroll
            for (int it = 0; it < 4; it++) {
                const int n = bid * 32 + wid * 4 + it;
                float m0 = 0.f, m1 = 0.f;
                #pragma unroll
                for (int zz = 0; zz < MSPLIT; zz++) {
                    m0 += g_Mpart[((size_t)zz * NN + n) * 64 + lane];
                    m1 += g_Mpart[((size_t)zz * NN + n) * 64 + 32 + lane];
                }
                const float h_old = g_HC[n * 64 + lane];
                const float c_old = g_HC[n * 64 + 32 + lane];
                sv[lane]      = m0;
                sv[32 + lane] = m1;
                sv[64 + lane] = h_old;
                if (lane < FIN) sv[96 + lane] = g_C1[(size_t)n * 1024 + t * FIN + lane];
                __syncwarp();

                u64 a01 = pack2(bb.x, bb.y);
                u64 a23 = pack2(bb.z, bb.w);
                #pragma unroll
                for (int k = 0; k < 101; k++) {
                    const float s = sv[k];
                    const u64 ss = pack2(s, s);
                    const float4 u4 = Us4[k * 32 + lane];
                    ffma2(a01, pack2(u4.x, u4.y), ss);
                    ffma2(a23, pack2(u4.z, u4.w), ss);
                }
                float gi, gf, gg, go;
                unpack2(a01, gi, gf);
                unpack2(a23, gg, go);

                const float ii = 1.f / (1.f + expf(-gi));
                const float ff = 1.f / (1.f + expf(-gf));
                const float g3 = tanhf(gg);
                const float oo = 1.f / (1.f + expf(-go));
                const float c_new = ff * c_old + ii * g3;
                const float h_new = oo * tanhf(c_new);
                g_HC[n * 64 + lane]      = h_new;
                g_HC[n * 64 + 32 + lane] = c_new;

                // B-tile writes (tile ktg = n>>7 at ktg<<14)
                const int ktg = n >> 7, kin = n & 127;
                const size_t tbase = (size_t)ktg << 14;
                const uint32_t kpart = (uint32_t)(((kin >> 3) & 0xF) << 4);
                const uint32_t klow  = (uint32_t)((kin & 7) * 2);
                char* const pBh = reinterpret_cast<char*>(g_Bh) + tbase;
                char* const pBl = reinterpret_cast<char*>(g_Bl) + tbase;

                __nv_bfloat16 hh = __float2bfloat16(h_new);
                __nv_bfloat16 hl = __float2bfloat16(h_new - __bfloat162float(hh));
                __nv_bfloat16 ch = __float2bfloat16(c_new);
                __nv_bfloat16 cl = __float2bfloat16(c_new - __bfloat162float(ch));

                const uint32_t bh_row = (uint32_t)lane;
                const uint32_t bc_row = (uint32_t)(lane + 32);
                const uint32_t offh = bh_row * 256 + (kpart ^ ((bh_row & 7) << 4)) + klow;
                const uint32_t offc = bc_row * 256 + (kpart ^ ((bc_row & 7) << 4)) + klow;
                *reinterpret_cast<__nv_bfloat16*>(pBh + offh) = hh;
                *reinterpret_cast<__nv_bfloat16*>(pBl + offh) = hl;
                *reinterpret_cast<__nv_bfloat16*>(pBh + offc) = ch;
                *reinterpret_cast<__nv_bfloat16*>(pBl + offc) = cl;
                __syncwarp();
            }
        }

        grid_sync(++bar * NCTA);
    }

    // ---- final projection for own nodes ----
    if (tid < 32) {
        const int n = bid * 32 + tid;
        float s = b_fc[0];
        #pragma unroll
        for (int u = 0; u < HDIM; u++) s += g_HC[n * 64 + u] * W_fc[u];
        out[n] = s;
    }
}

// ---------------- launch --------------------------------------------------------
extern "C" void kernel_launch(void* const* d_in, const int* in_sizes, int n_in,
                              void* d_out, int out_size) {
    const float* X    = (const float*)d_in[0];
    const float* A    = (const float*)d_in[1];
    const float* Wx   = (const float*)d_in[2];
    const float* Wh   = (const float*)d_in[3];
    const float* Wc   = (const float*)d_in[4];
    const float* W_ih = (const float*)d_in[5];
    const float* W_hh = (const float*)d_in[6];
    const float* b_ih = (const float*)d_in[7];
    const float* b_hh = (const float*)d_in[8];
    const float* W_fc = (const float*)d_in[9];
    const float* b_fc = (const float*)d_in[10];

    cudaFuncSetAttribute(c1_mma, cudaFuncAttributeMaxDynamicSharedMemorySize, 2 * STG_SZ);
    cudaFuncSetAttribute(fused_steps, cudaFuncAttributeMaxDynamicSharedMemorySize, 2 * STG_SZ);

    setup_kernel<<<1, 128>>>(Wx, Wh, Wc, W_ih, W_hh, b_ih, b_hh);
    zero_state_kernel<<<(NN * 64) / 256, 256>>>();
    xrconv_kernel<<<(1024 * 512) / 256, 256>>>(X);
    aconv_kernel<<<(NN * 512) / 256, 256>>>(A);
    c1_mma<<<dim3(32, 16), 256, 2 * STG_SZ>>>();
    fused_steps<<<NCTA, 256, 2 * STG_SZ>>>(W_fc, b_fc, (float*)d_out);
}

// round 12
// speedup vs baseline: 4.3788x; 1.5511x over previous
#include <cuda_runtime.h>
#include <cuda_fp16.h>
#include <math.h>
#include <cstdint>

// Problem constants
#define NN    4096
#define HDIM  32
#define TROLL 200
#define FIN   5

#define MSPLIT 4               // K-split for step GEMM; each CTA does K=1024
#define NKT    8               // k-tiles per step CTA
#define NCTA   128             // persistent grid size (mt*4 + z)

// fp16 scaling: A stored x4096 (avoids subnormals, exact [0,1) fit);
// B (h,c) stored x256 (subnormal-safe, overflow headroom to |c|~250).
#define A_SCALE   4096.0f
#define B_SCALE   256.0f
#define AB_INV    (1.0f / (4096.0f * 256.0f))   // step epilogue
#define A_INV     (1.0f / 4096.0f)              // c1 epilogue

typedef unsigned long long u64;

// ---------------- fp32x2 / mma helpers ---------------------------------------
__device__ __forceinline__ u64 pack2(float x, float y) {
    u64 r; asm("mov.b64 %0, {%1, %2};" : "=l"(r) : "f"(x), "f"(y)); return r;
}
__device__ __forceinline__ void unpack2(u64 v, float& x, float& y) {
    asm("mov.b64 {%0, %1}, %2;" : "=f"(x), "=f"(y) : "l"(v));
}
__device__ __forceinline__ void ffma2(u64& d, u64 a, u64 b) {
    asm("fma.rn.f32x2 %0, %1, %2, %0;" : "+l"(d) : "l"(a), "l"(b));
}
__device__ __forceinline__ uint32_t smem_u32(const void* p) {
    uint32_t a;
    asm("{ .reg .u64 t; cvta.to.shared.u64 t, %1; cvt.u32.u64 %0, t; }" : "=r"(a) : "l"(p));
    return a;
}
__device__ __forceinline__ void ldm_x4(uint32_t* r, uint32_t addr) {
    asm volatile("ldmatrix.sync.aligned.m8n8.x4.shared.b16 {%0,%1,%2,%3}, [%4];"
        : "=r"(r[0]), "=r"(r[1]), "=r"(r[2]), "=r"(r[3]) : "r"(addr));
}
__device__ __forceinline__ void mma_f16(float* d, const uint32_t* a, uint32_t b0, uint32_t b1) {
    asm volatile("mma.sync.aligned.m16n8k16.row.col.f32.f16.f16.f32 "
        "{%0,%1,%2,%3}, {%4,%5,%6,%7}, {%8,%9}, {%0,%1,%2,%3};"
        : "+f"(d[0]), "+f"(d[1]), "+f"(d[2]), "+f"(d[3])
        : "r"(a[0]), "r"(a[1]), "r"(a[2]), "r"(a[3]), "r"(b0), "r"(b1));
}
__device__ __forceinline__ void cp_async16(uint32_t saddr, const void* gaddr) {
    asm volatile("cp.async.cg.shared.global [%0], [%1], 16;"
        :: "r"(saddr), "l"(gaddr) : "memory");
}
#define CP_COMMIT() asm volatile("cp.async.commit_group;" ::: "memory")

// ---------------- device scratch ---------------------------------------------
__device__ __align__(16) float g_HC[NN * 64];                      // [n][0:32]=h,[32:64]=c
__device__ __align__(16) float g_Mpart[(size_t)MSPLIT * NN * 64];  // K-split partials
__device__ __align__(16) float g_C1[(size_t)NN * 1024];            // A @ Xr (fp32)
__device__ __align__(16) float g_U[101 * 128];
__device__ __align__(16) float g_bias[128];
__device__ __align__(16) float g_U4[13056];                        // [(k*32+l)*4+q]=U[k][l+32q]; +bias4
__device__ unsigned g_ctr;                                          // grid barrier counter
// A (x4096) fp16, ldmatrix-ready 128x128 tiles.
// tile (mt, ktg) at ((mt*32+ktg) << 15); byte(row,k)=row*256+(((k>>3)^(row&7))<<4)+(k&7)*2
__device__ __align__(16) __half g_Ah[(size_t)NN * NN];
// HC^T (x256) fp16, 64x128 tiles (16KB), tile ktg at (ktg<<14)
__device__ __align__(16) __half g_Bh[(size_t)64 * NN];
// Xr^T fp16 (unscaled), 64x128 tiles, tile (ktg,nt) at ((nt*32+ktg)<<14)
__device__ __align__(16) __half g_XBh[(size_t)1024 * NN];

// ---------------- setup: fused gate matrix U + repacked U4 -------------------
__global__ void setup_kernel(const float* __restrict__ Wx, const float* __restrict__ Wh,
                             const float* __restrict__ Wc, const float* __restrict__ W_ih,
                             const float* __restrict__ W_hh, const float* __restrict__ b_ih,
                             const float* __restrict__ b_hh) {
    const int j = threadIdx.x;
    __shared__ float sWih[128 * 32];
    for (int i = j; i < 128 * 32; i += 128) sWih[i] = W_ih[i];
    __syncthreads();
    for (int r = 0; r < 32; r++) {
        float s = 0.f;
        for (int m = 0; m < 32; m++) s += Wh[r * 32 + m] * sWih[j * 32 + m];
        g_U[r * 128 + j] = s;
    }
    for (int r = 0; r < 32; r++) {
        float s = 0.f;
        for (int m = 0; m < 32; m++) s += Wc[r * 32 + m] * sWih[j * 32 + m];
        g_U[(32 + r) * 128 + j] = s;
    }
    for (int m = 0; m < 32; m++) g_U[(64 + m) * 128 + j] = W_hh[j * 32 + m];
    for (int f = 0; f < FIN; f++) {
        float s = 0.f;
        for (int m = 0; m < 32; m++) s += Wx[f * 32 + m] * sWih[j * 32 + m];
        g_U[(96 + f) * 128 + j] = s;
    }
    g_bias[j] = b_ih[j] + b_hh[j];
    __syncthreads();
    {
        const int l = j & 31, q = j >> 5;
        for (int k = 0; k < 101; k++)
            g_U4[(k * 32 + l) * 4 + q] = g_U[k * 128 + l + 32 * q];
        g_U4[(101 * 32 + l) * 4 + q] = g_bias[l + 32 * q];
    }
}

// Zero h/c, B tiles, and barrier counter (graph-replay determinism).
__global__ void zero_state_kernel() {
    int i = blockIdx.x * blockDim.x + threadIdx.x;   // 262144 threads
    g_HC[i] = 0.f;
    g_Bh[i] = __float2half(0.f);
    if (i == 0) g_ctr = 0u;
}

// ---------------- A -> fp16 (x4096) ldmatrix tiles (once) ---------------------
__global__ void aconv_kernel(const float* __restrict__ A) {
    int idx = blockIdx.x * blockDim.x + threadIdx.x;   // NN*512 threads, 8 elems each
    int r = idx >> 9;
    int k = (idx & 511) << 3;
    int mt = r >> 7, rin = r & 127;
    int ktg = k >> 7, kin = k & 127;
    uint32_t byte = (uint32_t)(rin * 256 + ((((kin >> 3)) ^ (rin & 7)) << 4));
    size_t tile = ((size_t)(mt * 32 + ktg)) << 15;
    unsigned short h[8];
    #pragma unroll
    for (int i = 0; i < 8; i++) {
        float x = A[(size_t)r * NN + k + i] * A_SCALE;
        h[i] = __half_as_ushort(__float2half(x));
    }
    uint4 vh = make_uint4((uint32_t)h[0] | ((uint32_t)h[1] << 16),
                          (uint32_t)h[2] | ((uint32_t)h[3] << 16),
                          (uint32_t)h[4] | ((uint32_t)h[5] << 16),
                          (uint32_t)h[6] | ((uint32_t)h[7] << 16));
    *reinterpret_cast<uint4*>(reinterpret_cast<char*>(g_Ah) + tile + byte) = vh;
}

// ---------------- X -> Xr^T fp16 ldmatrix tiles (once) ------------------------
__global__ void xrconv_kernel(const float* __restrict__ X) {
    int idx = blockIdx.x * blockDim.x + threadIdx.x;   // 1024*512 threads
    int q  = idx >> 9;
    int kk = (idx & 511) << 3;
    int nt = q >> 6, rown = q & 63;
    int ktg = kk >> 7, kin = kk & 127;
    uint32_t byte = (uint32_t)(rown * 256 + ((((kin >> 3)) ^ (rown & 7)) << 4));
    size_t tile = ((size_t)(nt * 32 + ktg)) << 14;
    const bool valid = (q < TROLL * FIN);
    const int t = q / FIN, f = q - t * FIN;
    unsigned short h[8];
    #pragma unroll
    for (int i = 0; i < 8; i++) {
        float x = valid ? X[((size_t)t * NN + kk + i) * FIN + f] : 0.f;
        h[i] = __half_as_ushort(__float2half(x));
    }
    uint4 vh = make_uint4((uint32_t)h[0] | ((uint32_t)h[1] << 16),
                          (uint32_t)h[2] | ((uint32_t)h[3] << 16),
                          (uint32_t)h[4] | ((uint32_t)h[5] << 16),
                          (uint32_t)h[6] | ((uint32_t)h[7] << 16));
    *reinterpret_cast<uint4*>(reinterpret_cast<char*>(g_XBh) + tile + byte) = vh;
}

// ---------------- shared SMEM stage layout ------------------------------------
#define STG_SZ 49152          // A 32K | B 16K
#define SM_B   32768

// ---------------- C1 = A @ Xr via single fp16 mma (one-time) -------------------
__global__ void __launch_bounds__(256, 1) c1_mma() {
    extern __shared__ __align__(16) char smem[];
    const int tid  = threadIdx.x;
    const int lane = tid & 31;
    const int wid  = tid >> 5;
    const int wm   = wid & 3;
    const int wn   = wid >> 2;
    const int mt   = blockIdx.x;
    const int nt   = blockIdx.y;
    const uint32_t sbase = smem_u32(smem);

    auto load_tile = [&](int kt, int b) {
        const char* gA = reinterpret_cast<const char*>(g_Ah) + (((size_t)(mt * 32 + kt)) << 15);
        const char* gB = reinterpret_cast<const char*>(g_XBh) + (((size_t)(nt * 32 + kt)) << 14);
        const uint32_t s = sbase + b * STG_SZ;
        #pragma unroll
        for (int i = 0; i < 8; i++)
            cp_async16(s + (tid + i * 256) * 16, gA + (tid + i * 256) * 16);
        #pragma unroll
        for (int i = 0; i < 4; i++)
            cp_async16(s + SM_B + (tid + i * 256) * 16, gB + (tid + i * 256) * 16);
        CP_COMMIT();
    };

    float acc[2][4][4];
    #pragma unroll
    for (int im = 0; im < 2; im++)
        #pragma unroll
        for (int jn = 0; jn < 4; jn++)
            #pragma unroll
            for (int q = 0; q < 4; q++) acc[im][jn][q] = 0.f;

    load_tile(0, 0);
    load_tile(1, 1);

    const int arow[2] = { wm * 32 + (lane & 15), wm * 32 + 16 + (lane & 15) };
    const int acolh   = (lane >> 4);
    const int nrow[2] = { wn * 32 + (lane & 7) + ((lane >> 4) << 3),
                          wn * 32 + 16 + (lane & 7) + ((lane >> 4) << 3) };
    const int bcolh   = (lane >> 3) & 1;

    for (int kt = 0; kt < 32; kt++) {
        const int b = kt & 1;
        if (kt == 31) asm volatile("cp.async.wait_group 0;" ::: "memory");
        else          asm volatile("cp.async.wait_group 1;" ::: "memory");
        __syncthreads();

        const uint32_t sA = sbase + b * STG_SZ;
        const uint32_t sB = sA + SM_B;

        #pragma unroll
        for (int ks = 0; ks < 8; ks++) {
            const int ck = ks * 2;
            uint32_t ah[2][4], bh[2][4];
            #pragma unroll
            for (int im = 0; im < 2; im++) {
                const int r = arow[im];
                ldm_x4(ah[im], sA + (uint32_t)(r * 256 + (((ck + acolh) ^ (r & 7)) << 4)));
            }
            #pragma unroll
            for (int g = 0; g < 2; g++) {
                const int r = nrow[g];
                ldm_x4(bh[g], sB + (uint32_t)(r * 256 + (((ck + bcolh) ^ (r & 7)) << 4)));
            }
            #pragma unroll
            for (int im = 0; im < 2; im++)
                #pragma unroll
                for (int jn = 0; jn < 4; jn++) {
                    const int g = jn >> 1, w = (jn & 1) * 2;
                    mma_f16(acc[im][jn], ah[im], bh[g][w], bh[g][w + 1]);
                }
        }
        __syncthreads();
        if (kt + 2 < 32) load_tile(kt + 2, b);
    }

    const int row0 = mt * 128 + wm * 32 + (lane >> 2);
    const int col0 = nt * 64 + wn * 32 + (lane & 3) * 2;
    #pragma unroll
    for (int im = 0; im < 2; im++)
        #pragma unroll
        for (int jn = 0; jn < 4; jn++) {
            const int r = row0 + im * 16;
            const int c = col0 + jn * 8;
            *reinterpret_cast<float2*>(&g_C1[(size_t)r * 1024 + c]) =
                make_float2(acc[im][jn][0] * A_INV, acc[im][jn][1] * A_INV);
            *reinterpret_cast<float2*>(&g_C1[(size_t)(r + 8) * 1024 + c]) =
                make_float2(acc[im][jn][2] * A_INV, acc[im][jn][3] * A_INV);
        }
}

// ---------------- grid barrier (persistent kernel) -----------------------------
__device__ __forceinline__ void grid_sync(unsigned goal) {
    __syncthreads();
    if (threadIdx.x == 0) {
        __threadfence();
        atomicAdd(&g_ctr, 1u);
        unsigned v;
        do {
            asm volatile("ld.acquire.gpu.global.u32 %0, [%1];" : "=r"(v) : "l"(&g_ctr) : "memory");
        } while (v < goal);
    }
    __syncthreads();
}

// ---------------- persistent fused step loop -----------------------------------
__global__ void __launch_bounds__(256, 1) fused_steps(const float* __restrict__ W_fc,
                                                      const float* __restrict__ b_fc,
                                                      float* __restrict__ out) {
    extern __shared__ __align__(16) char smem[];
    const int tid  = threadIdx.x;
    const int lane = tid & 31;
    const int wid  = tid >> 5;
    const int wm   = wid & 3;
    const int wn   = wid >> 2;
    const int bid  = blockIdx.x;
    const int mt   = bid >> 2;
    const int z    = bid & 3;
    const uint32_t sbase = smem_u32(smem);

    auto load_tile = [&](int kt, int b) {
        const int ktg = z * NKT + kt;
        const char* gA = reinterpret_cast<const char*>(g_Ah) + (((size_t)(mt * 32 + ktg)) << 15);
        const char* gB = reinterpret_cast<const char*>(g_Bh) + ((size_t)ktg << 14);
        const uint32_t s = sbase + b * STG_SZ;
        #pragma unroll
        for (int i = 0; i < 8; i++)
            cp_async16(s + (tid + i * 256) * 16, gA + (tid + i * 256) * 16);
        #pragma unroll
        for (int i = 0; i < 4; i++)
            cp_async16(s + SM_B + (tid + i * 256) * 16, gB + (tid + i * 256) * 16);
        CP_COMMIT();
    };

    const int arow[2] = { wm * 32 + (lane & 15), wm * 32 + 16 + (lane & 15) };
    const int acolh   = (lane >> 4);
    const int nrow[2] = { wn * 32 + (lane & 7) + ((lane >> 4) << 3),
                          wn * 32 + 16 + (lane & 7) + ((lane >> 4) << 3) };
    const int bcolh   = (lane >> 3) & 1;

    unsigned bar = 0;

    for (int t = 0; t < TROLL; t++) {
        // ================= phase A: step GEMM (single fp16 product) ==========
        float acc[2][4][4];
        #pragma unroll
        for (int im = 0; im < 2; im++)
            #pragma unroll
            for (int jn = 0; jn < 4; jn++)
                #pragma unroll
                for (int q = 0; q < 4; q++) acc[im][jn][q] = 0.f;

        load_tile(0, 0);
        load_tile(1, 1);

        #pragma unroll
        for (int kt = 0; kt < NKT; kt++) {
            const int b = kt & 1;
            if (kt == NKT - 1) asm volatile("cp.async.wait_group 0;" ::: "memory");
            else               asm volatile("cp.async.wait_group 1;" ::: "memory");
            __syncthreads();

            const uint32_t sA = sbase + b * STG_SZ;
            const uint32_t sB = sA + SM_B;

            #pragma unroll
            for (int ks = 0; ks < 8; ks++) {
                const int ck = ks * 2;
                uint32_t ah[2][4], bh[2][4];
                #pragma unroll
                for (int im = 0; im < 2; im++) {
                    const int r = arow[im];
                    ldm_x4(ah[im], sA + (uint32_t)(r * 256 + (((ck + acolh) ^ (r & 7)) << 4)));
                }
                #pragma unroll
                for (int g = 0; g < 2; g++) {
                    const int r = nrow[g];
                    ldm_x4(bh[g], sB + (uint32_t)(r * 256 + (((ck + bcolh) ^ (r & 7)) << 4)));
                }
                #pragma unroll
                for (int im = 0; im < 2; im++)
                    #pragma unroll
                    for (int jn = 0; jn < 4; jn++) {
                        const int g = jn >> 1, w = (jn & 1) * 2;
                        mma_f16(acc[im][jn], ah[im], bh[g][w], bh[g][w + 1]);
                    }
            }
            __syncthreads();
            if (kt + 2 < NKT) load_tile(kt + 2, b);
        }

        {
            float* base = g_Mpart + (size_t)z * NN * 64;
            const int row0 = mt * 128 + wm * 32 + (lane >> 2);
            const int col0 = wn * 32 + (lane & 3) * 2;
            #pragma unroll
            for (int im = 0; im < 2; im++)
                #pragma unroll
                for (int jn = 0; jn < 4; jn++) {
                    const int r = row0 + im * 16;
                    const int c = col0 + jn * 8;
                    *reinterpret_cast<float2*>(&base[(size_t)r * 64 + c]) =
                        make_float2(acc[im][jn][0] * AB_INV, acc[im][jn][1] * AB_INV);
                    *reinterpret_cast<float2*>(&base[(size_t)(r + 8) * 64 + c]) =
                        make_float2(acc[im][jn][2] * AB_INV, acc[im][jn][3] * AB_INV);
                }
        }

        grid_sync(++bar * NCTA);

        // ================= phase B: gates (overlay smem) =================
        {
            float4* Us4 = reinterpret_cast<float4*>(smem);
            const float4* gU4 = reinterpret_cast<const float4*>(g_U4);
            for (int i = tid; i < 3264; i += 256) Us4[i] = gU4[i];
            float* svall = reinterpret_cast<float*>(Us4 + 3264);
            __syncthreads();

            float* sv = svall + wid * 104;
            const float4 bb = Us4[3232 + lane];

            #pragma unroll
            for (int it = 0; it < 4; it++) {
                const int n = bid * 32 + wid * 4 + it;
                float m0 = 0.f, m1 = 0.f;
                #pragma unroll
                for (int zz = 0; zz < MSPLIT; zz++) {
                    m0 += g_Mpart[((size_t)zz * NN + n) * 64 + lane];
                    m1 += g_Mpart[((size_t)zz * NN + n) * 64 + 32 + lane];
                }
                const float h_old = g_HC[n * 64 + lane];
                const float c_old = g_HC[n * 64 + 32 + lane];
                sv[lane]      = m0;
                sv[32 + lane] = m1;
                sv[64 + lane] = h_old;
                if (lane < FIN) sv[96 + lane] = g_C1[(size_t)n * 1024 + t * FIN + lane];
                __syncwarp();

                u64 a01 = pack2(bb.x, bb.y);
                u64 a23 = pack2(bb.z, bb.w);
                #pragma unroll
                for (int k = 0; k < 101; k++) {
                    const float s = sv[k];
                    const u64 ss = pack2(s, s);
                    const float4 u4 = Us4[k * 32 + lane];
                    ffma2(a01, pack2(u4.x, u4.y), ss);
                    ffma2(a23, pack2(u4.z, u4.w), ss);
                }
                float gi, gf, gg, go;
                unpack2(a01, gi, gf);
                unpack2(a23, gg, go);

                const float ii = 1.f / (1.f + expf(-gi));
                const float ff = 1.f / (1.f + expf(-gf));
                const float g3 = tanhf(gg);
                const float oo = 1.f / (1.f + expf(-go));
                const float c_new = ff * c_old + ii * g3;
                const float h_new = oo * tanhf(c_new);
                g_HC[n * 64 + lane]      = h_new;
                g_HC[n * 64 + 32 + tid % 32] = c_new;   // lane == tid%32

                // B-tile writes (fp16, x256; tile ktg = n>>7 at ktg<<14)
                const int ktg = n >> 7, kin = n & 127;
                const size_t tbase = (size_t)ktg << 14;
                const uint32_t kpart = (uint32_t)(((kin >> 3) & 0xF) << 4);
                const uint32_t klow  = (uint32_t)((kin & 7) * 2);
                char* const pB = reinterpret_cast<char*>(g_Bh) + tbase;

                const __half hh = __float2half(h_new * B_SCALE);
                const __half ch = __float2half(c_new * B_SCALE);

                const uint32_t bh_row = (uint32_t)lane;
                const uint32_t bc_row = (uint32_t)(lane + 32);
                const uint32_t offh = bh_row * 256 + (kpart ^ ((bh_row & 7) << 4)) + klow;
                const uint32_t offc = bc_row * 256 + (kpart ^ ((bc_row & 7) << 4)) + klow;
                *reinterpret_cast<__half*>(pB + offh) = hh;
                *reinterpret_cast<__half*>(pB + offc) = ch;
                __syncwarp();
            }
        }

        grid_sync(++bar * NCTA);
    }

    // ---- final projection for own nodes ----
    if (tid < 32) {
        const int n = bid * 32 + tid;
        float s = b_fc[0];
        #pragma unroll
        for (int u = 0; u < HDIM; u++) s += g_HC[n * 64 + u] * W_fc[u];
        out[n] = s;
    }
}

// ---------------- launch --------------------------------------------------------
extern "C" void kernel_launch(void* const* d_in, const int* in_sizes, int n_in,
                              void* d_out, int out_size) {
    const float* X    = (const float*)d_in[0];
    const float* A    = (const float*)d_in[1];
    const float* Wx   = (const float*)d_in[2];
    const float* Wh   = (const float*)d_in[3];
    const float* Wc   = (const float*)d_in[4];
    const float* W_ih = (const float*)d_in[5];
    const float* W_hh = (const float*)d_in[6];
    const float* b_ih = (const float*)d_in[7];
    const float* b_hh = (const float*)d_in[8];
    const float* W_fc = (const float*)d_in[9];
    const float* b_fc = (const float*)d_in[10];

    cudaFuncSetAttribute(c1_mma, cudaFuncAttributeMaxDynamicSharedMemorySize, 2 * STG_SZ);
    cudaFuncSetAttribute(fused_steps, cudaFuncAttributeMaxDynamicSharedMemorySize, 2 * STG_SZ);

    setup_kernel<<<1, 128>>>(Wx, Wh, Wc, W_ih, W_hh, b_ih, b_hh);
    zero_state_kernel<<<(NN * 64) / 256, 256>>>();
    xrconv_kernel<<<(1024 * 512) / 256, 256>>>(X);
    aconv_kernel<<<(NN * 512) / 256, 256>>>(A);
    c1_mma<<<dim3(32, 16), 256, 2 * STG_SZ>>>();
    fused_steps<<<NCTA, 256, 2 * STG_SZ>>>(W_fc, b_fc, (float*)d_out);
}

// round 13
// speedup vs baseline: 4.5607x; 1.0415x over previous
#include <cuda_runtime.h>
#include <cuda_fp16.h>
#include <math.h>
#include <cstdint>

// Problem constants
#define NN    4096
#define HDIM  32
#define TROLL 200
#define FIN   5

#define MSPLIT 4               // K-split for step GEMM; each CTA does K=1024
#define NKT    8               // k-tiles per step CTA
#define NCTA   128             // persistent grid size (mt*4 + z)

// fp16 scaling: A stored x4096 (avoids subnormals); B (h,c) stored x256.
#define A_SCALE   4096.0f
#define B_SCALE   256.0f
#define AB_INV    (1.0f / (4096.0f * 256.0f))
#define A_INV     (1.0f / 4096.0f)

typedef unsigned long long u64;

// ---------------- fp32x2 / mma helpers ---------------------------------------
__device__ __forceinline__ u64 pack2(float x, float y) {
    u64 r; asm("mov.b64 %0, {%1, %2};" : "=l"(r) : "f"(x), "f"(y)); return r;
}
__device__ __forceinline__ void unpack2(u64 v, float& x, float& y) {
    asm("mov.b64 {%0, %1}, %2;" : "=f"(x), "=f"(y) : "l"(v));
}
__device__ __forceinline__ void ffma2(u64& d, u64 a, u64 b) {
    asm("fma.rn.f32x2 %0, %1, %2, %0;" : "+l"(d) : "l"(a), "l"(b));
}
__device__ __forceinline__ uint32_t smem_u32(const void* p) {
    uint32_t a;
    asm("{ .reg .u64 t; cvta.to.shared.u64 t, %1; cvt.u32.u64 %0, t; }" : "=r"(a) : "l"(p));
    return a;
}
__device__ __forceinline__ void ldm_x4(uint32_t* r, uint32_t addr) {
    asm volatile("ldmatrix.sync.aligned.m8n8.x4.shared.b16 {%0,%1,%2,%3}, [%4];"
        : "=r"(r[0]), "=r"(r[1]), "=r"(r[2]), "=r"(r[3]) : "r"(addr));
}
__device__ __forceinline__ void mma_f16(float* d, const uint32_t* a, uint32_t b0, uint32_t b1) {
    asm volatile("mma.sync.aligned.m16n8k16.row.col.f32.f16.f16.f32 "
        "{%0,%1,%2,%3}, {%4,%5,%6,%7}, {%8,%9}, {%0,%1,%2,%3};"
        : "+f"(d[0]), "+f"(d[1]), "+f"(d[2]), "+f"(d[3])
        : "r"(a[0]), "r"(a[1]), "r"(a[2]), "r"(a[3]), "r"(b0), "r"(b1));
}
__device__ __forceinline__ void cp_async16(uint32_t saddr, const void* gaddr) {
    asm volatile("cp.async.cg.shared.global [%0], [%1], 16;"
        :: "r"(saddr), "l"(gaddr) : "memory");
}
#define CP_COMMIT() asm volatile("cp.async.commit_group;" ::: "memory")

// ---------------- device scratch ---------------------------------------------
__device__ __align__(16) float g_HC[NN * 64];                      // [n][0:32]=h,[32:64]=c
__device__ __align__(16) float g_Mpart[(size_t)MSPLIT * NN * 64];  // K-split partials
__device__ __align__(16) float g_C1[(size_t)NN * 1024];            // A @ Xr (fp32)
__device__ __align__(16) float g_U[101 * 128];
__device__ __align__(16) float g_bias[128];
__device__ __align__(16) float g_U4[13056];                        // [(k*32+l)*4+q]=U[k][l+32q]; +bias4
__device__ unsigned g_ctr;                                          // grid barrier counter
// A (x4096) fp16, ldmatrix-ready 128x128 tiles.
// tile (mt, ktg) at ((mt*32+ktg) << 15); byte(row,k)=row*256+(((k>>3)^(row&7))<<4)+(k&7)*2
__device__ __align__(16) __half g_Ah[(size_t)NN * NN];
// HC^T (x256) fp16, 64x128 tiles (16KB), tile ktg at (ktg<<14)
__device__ __align__(16) __half g_Bh[(size_t)64 * NN];
// Xr^T fp16, 64x128 tiles, tile (ktg,nt) at ((nt*32+ktg)<<14)
__device__ __align__(16) __half g_XBh[(size_t)1024 * NN];

// ---------------- setup: fused gate matrix U + repacked U4 -------------------
__global__ void setup_kernel(const float* __restrict__ Wx, const float* __restrict__ Wh,
                             const float* __restrict__ Wc, const float* __restrict__ W_ih,
                             const float* __restrict__ W_hh, const float* __restrict__ b_ih,
                             const float* __restrict__ b_hh) {
    const int j = threadIdx.x;
    __shared__ float sWih[128 * 32];
    for (int i = j; i < 128 * 32; i += 128) sWih[i] = W_ih[i];
    __syncthreads();
    for (int r = 0; r < 32; r++) {
        float s = 0.f;
        for (int m = 0; m < 32; m++) s += Wh[r * 32 + m] * sWih[j * 32 + m];
        g_U[r * 128 + j] = s;
    }
    for (int r = 0; r < 32; r++) {
        float s = 0.f;
        for (int m = 0; m < 32; m++) s += Wc[r * 32 + m] * sWih[j * 32 + m];
        g_U[(32 + r) * 128 + j] = s;
    }
    for (int m = 0; m < 32; m++) g_U[(64 + m) * 128 + j] = W_hh[j * 32 + m];
    for (int f = 0; f < FIN; f++) {
        float s = 0.f;
        for (int m = 0; m < 32; m++) s += Wx[f * 32 + m] * sWih[j * 32 + m];
        g_U[(96 + f) * 128 + j] = s;
    }
    g_bias[j] = b_ih[j] + b_hh[j];
    __syncthreads();
    {
        const int l = j & 31, q = j >> 5;
        for (int k = 0; k < 101; k++)
            g_U4[(k * 32 + l) * 4 + q] = g_U[k * 128 + l + 32 * q];
        g_U4[(101 * 32 + l) * 4 + q] = g_bias[l + 32 * q];
    }
}

// Zero h/c, B tiles, and barrier counter (graph-replay determinism).
__global__ void zero_state_kernel() {
    int i = blockIdx.x * blockDim.x + threadIdx.x;   // 262144 threads
    g_HC[i] = 0.f;
    g_Bh[i] = __float2half(0.f);
    if (i == 0) g_ctr = 0u;
}

// ---------------- A -> fp16 (x4096) ldmatrix tiles (once) ---------------------
__global__ void aconv_kernel(const float* __restrict__ A) {
    int idx = blockIdx.x * blockDim.x + threadIdx.x;
    int r = idx >> 9;
    int k = (idx & 511) << 3;
    int mt = r >> 7, rin = r & 127;
    int ktg = k >> 7, kin = k & 127;
    uint32_t byte = (uint32_t)(rin * 256 + ((((kin >> 3)) ^ (rin & 7)) << 4));
    size_t tile = ((size_t)(mt * 32 + ktg)) << 15;
    unsigned short h[8];
    #pragma unroll
    for (int i = 0; i < 8; i++) {
        float x = A[(size_t)r * NN + k + i] * A_SCALE;
        h[i] = __half_as_ushort(__float2half(x));
    }
    uint4 vh = make_uint4((uint32_t)h[0] | ((uint32_t)h[1] << 16),
                          (uint32_t)h[2] | ((uint32_t)h[3] << 16),
                          (uint32_t)h[4] | ((uint32_t)h[5] << 16),
                          (uint32_t)h[6] | ((uint32_t)h[7] << 16));
    *reinterpret_cast<uint4*>(reinterpret_cast<char*>(g_Ah) + tile + byte) = vh;
}

// ---------------- X -> Xr^T fp16 ldmatrix tiles (once) ------------------------
__global__ void xrconv_kernel(const float* __restrict__ X) {
    int idx = blockIdx.x * blockDim.x + threadIdx.x;
    int q  = idx >> 9;
    int kk = (idx & 511) << 3;
    int nt = q >> 6, rown = q & 63;
    int ktg = kk >> 7, kin = kk & 127;
    uint32_t byte = (uint32_t)(rown * 256 + ((((kin >> 3)) ^ (rown & 7)) << 4));
    size_t tile = ((size_t)(nt * 32 + ktg)) << 14;
    const bool valid = (q < TROLL * FIN);
    const int t = q / FIN, f = q - t * FIN;
    unsigned short h[8];
    #pragma unroll
    for (int i = 0; i < 8; i++) {
        float x = valid ? X[((size_t)t * NN + kk + i) * FIN + f] : 0.f;
        h[i] = __half_as_ushort(__float2half(x));
    }
    uint4 vh = make_uint4((uint32_t)h[0] | ((uint32_t)h[1] << 16),
                          (uint32_t)h[2] | ((uint32_t)h[3] << 16),
                          (uint32_t)h[4] | ((uint32_t)h[5] << 16),
                          (uint32_t)h[6] | ((uint32_t)h[7] << 16));
    *reinterpret_cast<uint4*>(reinterpret_cast<char*>(g_XBh) + tile + byte) = vh;
}

// ---------------- SMEM layout --------------------------------------------------
#define STG    49152          // stage: A 32K | B 16K
#define SM_B   32768
#define U_OFF  (3 * STG)                 // 147456: persistent U4 (52224 B)
#define SV_OFF (U_OFF + 52224)           // 199680: sv scratch (3328 B)
#define FS_SMEM (SV_OFF + 3328)          // 203008 total
#define C1_SMEM (2 * STG)

// ---------------- C1 = A @ Xr via single fp16 mma (one-time) -------------------
__global__ void __launch_bounds__(256, 1) c1_mma() {
    extern __shared__ __align__(16) char smem[];
    const int tid  = threadIdx.x;
    const int lane = tid & 31;
    const int wid  = tid >> 5;
    const int wm   = wid & 3;
    const int wn   = wid >> 2;
    const int mt   = blockIdx.x;
    const int nt   = blockIdx.y;
    const uint32_t sbase = smem_u32(smem);

    auto load_tile = [&](int kt, int b) {
        const char* gA = reinterpret_cast<const char*>(g_Ah) + (((size_t)(mt * 32 + kt)) << 15);
        const char* gB = reinterpret_cast<const char*>(g_XBh) + (((size_t)(nt * 32 + kt)) << 14);
        const uint32_t s = sbase + b * STG;
        #pragma unroll
        for (int i = 0; i < 8; i++)
            cp_async16(s + (tid + i * 256) * 16, gA + (tid + i * 256) * 16);
        #pragma unroll
        for (int i = 0; i < 4; i++)
            cp_async16(s + SM_B + (tid + i * 256) * 16, gB + (tid + i * 256) * 16);
        CP_COMMIT();
    };

    float acc[2][4][4];
    #pragma unroll
    for (int im = 0; im < 2; im++)
        #pragma unroll
        for (int jn = 0; jn < 4; jn++)
            #pragma unroll
            for (int q = 0; q < 4; q++) acc[im][jn][q] = 0.f;

    load_tile(0, 0);
    load_tile(1, 1);

    const int arow[2] = { wm * 32 + (lane & 15), wm * 32 + 16 + (lane & 15) };
    const int acolh   = (lane >> 4);
    const int nrow[2] = { wn * 32 + (lane & 7) + ((lane >> 4) << 3),
                          wn * 32 + 16 + (lane & 7) + ((lane >> 4) << 3) };
    const int bcolh   = (lane >> 3) & 1;

    for (int kt = 0; kt < 32; kt++) {
        const int b = kt & 1;
        if (kt == 31) asm volatile("cp.async.wait_group 0;" ::: "memory");
        else          asm volatile("cp.async.wait_group 1;" ::: "memory");
        __syncthreads();

        const uint32_t sA = sbase + b * STG;
        const uint32_t sB = sA + SM_B;

        #pragma unroll
        for (int ks = 0; ks < 8; ks++) {
            const int ck = ks * 2;
            uint32_t ah[2][4], bh[2][4];
            #pragma unroll
            for (int im = 0; im < 2; im++) {
                const int r = arow[im];
                ldm_x4(ah[im], sA + (uint32_t)(r * 256 + (((ck + acolh) ^ (r & 7)) << 4)));
            }
            #pragma unroll
            for (int g = 0; g < 2; g++) {
                const int r = nrow[g];
                ldm_x4(bh[g], sB + (uint32_t)(r * 256 + (((ck + bcolh) ^ (r & 7)) << 4)));
            }
            #pragma unroll
            for (int im = 0; im < 2; im++)
                #pragma unroll
                for (int jn = 0; jn < 4; jn++) {
                    const int g = jn >> 1, w = (jn & 1) * 2;
                    mma_f16(acc[im][jn], ah[im], bh[g][w], bh[g][w + 1]);
                }
        }
        __syncthreads();
        if (kt + 2 < 32) load_tile(kt + 2, b);
    }

    const int row0 = mt * 128 + wm * 32 + (lane >> 2);
    const int col0 = nt * 64 + wn * 32 + (lane & 3) * 2;
    #pragma unroll
    for (int im = 0; im < 2; im++)
        #pragma unroll
        for (int jn = 0; jn < 4; jn++) {
            const int r = row0 + im * 16;
            const int c = col0 + jn * 8;
            *reinterpret_cast<float2*>(&g_C1[(size_t)r * 1024 + c]) =
                make_float2(acc[im][jn][0] * A_INV, acc[im][jn][1] * A_INV);
            *reinterpret_cast<float2*>(&g_C1[(size_t)(r + 8) * 1024 + c]) =
                make_float2(acc[im][jn][2] * A_INV, acc[im][jn][3] * A_INV);
        }
}

// ---------------- grid barrier (persistent kernel) -----------------------------
__device__ __forceinline__ void grid_sync(unsigned goal) {
    __syncthreads();
    if (threadIdx.x == 0) {
        __threadfence();
        atomicAdd(&g_ctr, 1u);
        unsigned v;
        do {
            asm volatile("ld.acquire.gpu.global.u32 %0, [%1];" : "=r"(v) : "l"(&g_ctr) : "memory");
        } while (v < goal);
    }
    __syncthreads();
}

// ---------------- persistent fused step loop -----------------------------------
// 3-stage pipeline (kt mod 3), persistent U table in smem, cross-barrier A prefetch.
__global__ void __launch_bounds__(256, 1) fused_steps(const float* __restrict__ W_fc,
                                                      const float* __restrict__ b_fc,
                                                      float* __restrict__ out) {
    extern __shared__ __align__(16) char smem[];
    const int tid  = threadIdx.x;
    const int lane = tid & 31;
    const int wid  = tid >> 5;
    const int wm   = wid & 3;
    const int wn   = wid >> 2;
    const int bid  = blockIdx.x;
    const int mt   = bid >> 2;
    const int z    = bid & 3;
    const uint32_t sbase = smem_u32(smem);

    // persistent U table (loaded once)
    float4* Us4 = reinterpret_cast<float4*>(smem + U_OFF);
    {
        const float4* gU4 = reinterpret_cast<const float4*>(g_U4);
        for (int i = tid; i < 3264; i += 256) Us4[i] = gU4[i];
    }
    float* svall = reinterpret_cast<float*>(smem + SV_OFF);
    __syncthreads();

    auto issueA = [&](int kt) {               // A half of tile kt -> stage kt%3
        const char* gA = reinterpret_cast<const char*>(g_Ah)
                       + (((size_t)(mt * 32 + z * 8 + kt)) << 15);
        const uint32_t d = sbase + (kt % 3) * STG;
        #pragma unroll
        for (int i = 0; i < 8; i++)
            cp_async16(d + (tid + i * 256) * 16, gA + (tid + i * 256) * 16);
    };
    auto issueB = [&](int kt) {               // B half of tile kt -> stage kt%3 + SM_B
        const char* gB = reinterpret_cast<const char*>(g_Bh)
                       + ((size_t)(z * 8 + kt) << 14);
        const uint32_t d = sbase + (kt % 3) * STG + SM_B;
        #pragma unroll
        for (int i = 0; i < 4; i++)
            cp_async16(d + (tid + i * 256) * 16, gB + (tid + i * 256) * 16);
    };

    const int arow[2] = { wm * 32 + (lane & 15), wm * 32 + 16 + (lane & 15) };
    const int acolh   = (lane >> 4);
    const int nrow[2] = { wn * 32 + (lane & 7) + ((lane >> 4) << 3),
                          wn * 32 + 16 + (lane & 7) + ((lane >> 4) << 3) };
    const int bcolh   = (lane >> 3) & 1;

    // prefetch A for step 0 tiles 0,1 (two groups)
    issueA(0); CP_COMMIT();
    issueA(1); CP_COMMIT();

    unsigned bar = 0;

    for (int t = 0; t < TROLL; t++) {
        // B halves for tiles 0,1 (one group); full tile 2 (one group)
        issueB(0); issueB(1); CP_COMMIT();
        issueA(2); issueB(2); CP_COMMIT();

        float acc[2][4][4];
        #pragma unroll
        for (int im = 0; im < 2; im++)
            #pragma unroll
            for (int jn = 0; jn < 4; jn++)
                #pragma unroll
                for (int q = 0; q < 4; q++) acc[im][jn][q] = 0.f;

        #pragma unroll
        for (int kt = 0; kt < NKT; kt++) {
            // hand-scheduled waits: 2 groups of lookahead in steady state
            if (kt == 0 || kt >= 6) asm volatile("cp.async.wait_group 1;" ::: "memory");
            else                    asm volatile("cp.async.wait_group 2;" ::: "memory");
            __syncthreads();

            const uint32_t sA = sbase + (kt % 3) * STG;
            const uint32_t sB = sA + SM_B;

            #pragma unroll
            for (int ks = 0; ks < 8; ks++) {
                const int ck = ks * 2;
                uint32_t ah[2][4], bh[2][4];
                #pragma unroll
                for (int im = 0; im < 2; im++) {
                    const int r = arow[im];
                    ldm_x4(ah[im], sA + (uint32_t)(r * 256 + (((ck + acolh) ^ (r & 7)) << 4)));
                }
                #pragma unroll
                for (int g = 0; g < 2; g++) {
                    const int r = nrow[g];
                    ldm_x4(bh[g], sB + (uint32_t)(r * 256 + (((ck + bcolh) ^ (r & 7)) << 4)));
                }
                #pragma unroll
                for (int im = 0; im < 2; im++)
                    #pragma unroll
                    for (int jn = 0; jn < 4; jn++) {
                        const int g = jn >> 1, w = (jn & 1) * 2;
                        mma_f16(acc[im][jn], ah[im], bh[g][w], bh[g][w + 1]);
                    }
            }
            __syncthreads();

            if (kt + 3 < NKT) { issueA(kt + 3); issueB(kt + 3); CP_COMMIT(); }
            else if (kt == 6) { issueA(0); CP_COMMIT(); }   // next-step A prefetch
            else if (kt == 7) { issueA(1); CP_COMMIT(); }
        }

        {
            float* base = g_Mpart + (size_t)z * NN * 64;
            const int row0 = mt * 128 + wm * 32 + (lane >> 2);
            const int col0 = wn * 32 + (lane & 3) * 2;
            #pragma unroll
            for (int im = 0; im < 2; im++)
                #pragma unroll
                for (int jn = 0; jn < 4; jn++) {
                    const int r = row0 + im * 16;
                    const int c = col0 + jn * 8;
                    *reinterpret_cast<float2*>(&base[(size_t)r * 64 + c]) =
                        make_float2(acc[im][jn][0] * AB_INV, acc[im][jn][1] * AB_INV);
                    *reinterpret_cast<float2*>(&base[(size_t)(r + 8) * 64 + c]) =
                        make_float2(acc[im][jn][2] * AB_INV, acc[im][jn][3] * AB_INV);
                }
        }

        grid_sync(++bar * NCTA);

        // ================= phase B: gates (persistent U) =================
        {
            float* sv = svall + wid * 104;
            const float4 bb = Us4[3232 + lane];

            #pragma unroll
            for (int it = 0; it < 4; it++) {
                const int n = bid * 32 + wid * 4 + it;
                float m0 = 0.f, m1 = 0.f;
                #pragma unroll
                for (int zz = 0; zz < MSPLIT; zz++) {
                    m0 += g_Mpart[((size_t)zz * NN + n) * 64 + lane];
                    m1 += g_Mpart[((size_t)zz * NN + n) * 64 + 32 + lane];
                }
                const float h_old = g_HC[n * 64 + lane];
                const float c_old = g_HC[n * 64 + 32 + lane];
                sv[lane]      = m0;
                sv[32 + lane] = m1;
                sv[64 + lane] = h_old;
                if (lane < FIN) sv[96 + lane] = g_C1[(size_t)n * 1024 + t * FIN + lane];
                __syncwarp();

                u64 a01 = pack2(bb.x, bb.y);
                u64 a23 = pack2(bb.z, bb.w);
                #pragma unroll
                for (int k = 0; k < 101; k++) {
                    const float s = sv[k];
                    const u64 ss = pack2(s, s);
                    const float4 u4 = Us4[k * 32 + lane];
                    ffma2(a01, pack2(u4.x, u4.y), ss);
                    ffma2(a23, pack2(u4.z, u4.w), ss);
                }
                float gi, gf, gg, go;
                unpack2(a01, gi, gf);
                unpack2(a23, gg, go);

                const float ii = 1.f / (1.f + expf(-gi));
                const float ff = 1.f / (1.f + expf(-gf));
                const float g3 = tanhf(gg);
                const float oo = 1.f / (1.f + expf(-go));
                const float c_new = ff * c_old + ii * g3;
                const float h_new = oo * tanhf(c_new);
                g_HC[n * 64 + lane]      = h_new;
                g_HC[n * 64 + 32 + lane] = c_new;

                // B-tile writes (fp16, x256; tile ktg = n>>7 at ktg<<14)
                const int ktg = n >> 7, kin = n & 127;
                const size_t tbase = (size_t)ktg << 14;
                const uint32_t kpart = (uint32_t)(((kin >> 3) & 0xF) << 4);
                const uint32_t klow  = (uint32_t)((kin & 7) * 2);
                char* const pB = reinterpret_cast<char*>(g_Bh) + tbase;

                const __half hh = __float2half(h_new * B_SCALE);
                const __half ch = __float2half(c_new * B_SCALE);

                const uint32_t bh_row = (uint32_t)lane;
                const uint32_t bc_row = (uint32_t)(lane + 32);
                const uint32_t offh = bh_row * 256 + (kpart ^ ((bh_row & 7) << 4)) + klow;
                const uint32_t offc = bc_row * 256 + (kpart ^ ((bc_row & 7) << 4)) + klow;
                *reinterpret_cast<__half*>(pB + offh) = hh;
                *reinterpret_cast<__half*>(pB + offc) = ch;
                __syncwarp();
            }
        }

        grid_sync(++bar * NCTA);
    }

    // ---- final projection for own nodes ----
    if (tid < 32) {
        const int n = bid * 32 + tid;
        float s = b_fc[0];
        #pragma unroll
        for (int u = 0; u < HDIM; u++) s += g_HC[n * 64 + u] * W_fc[u];
        out[n] = s;
    }
}

// ---------------- launch --------------------------------------------------------
extern "C" void kernel_launch(void* const* d_in, const int* in_sizes, int n_in,
                              void* d_out, int out_size) {
    const float* X    = (const float*)d_in[0];
    const float* A    = (const float*)d_in[1];
    const float* Wx   = (const float*)d_in[2];
    const float* Wh   = (const float*)d_in[3];
    const float* Wc   = (const float*)d_in[4];
    const float* W_ih = (const float*)d_in[5];
    const float* W_hh = (const float*)d_in[6];
    const float* b_ih = (const float*)d_in[7];
    const float* b_hh = (const float*)d_in[8];
    const float* W_fc = (const float*)d_in[9];
    const float* b_fc = (const float*)d_in[10];

    cudaFuncSetAttribute(c1_mma, cudaFuncAttributeMaxDynamicSharedMemorySize, C1_SMEM);
    cudaFuncSetAttribute(fused_steps, cudaFuncAttributeMaxDynamicSharedMemorySize, FS_SMEM);

    setup_kernel<<<1, 128>>>(Wx, Wh, Wc, W_ih, W_hh, b_ih, b_hh);
    zero_state_kernel<<<(NN * 64) / 256, 256>>>();
    xrconv_kernel<<<(1024 * 512) / 256, 256>>>(X);
    aconv_kernel<<<(NN * 512) / 256, 256>>>(A);
    c1_mma<<<dim3(32, 16), 256, C1_SMEM>>>();
    fused_steps<<<NCTA, 256, FS_SMEM>>>(W_fc, b_fc, (float*)d_out);
}